// round 3
// baseline (speedup 1.0000x reference)
#include <cuda_runtime.h>
#include <cstdint>

// ---------------------------------------------------------------------------
// DecoderRNNWithAttention — GB300 sm_103a, round 2
//  * attention is provably dead (softmax over 1 element) -> context==features
//  * input projection precomputed for all 25 steps (one GEMM)
//  * vocab projection batched over 24 emitted steps (one GEMM)
//  * NEW: cp.async 3-stage pipelined GEMMs (fp32 in SMEM, tf32 cvt at frag load)
//  * NEW: gate-permuted layout (4j+gate) -> LSTM cell fused into GEMM epilogue
//  * NEW: W_hh pre-split to tf32 hi/lo once per launch
// ---------------------------------------------------------------------------

constexpr int BB  = 128;
constexpr int TT  = 25;
constexpr int EE  = 512;
constexpr int HH  = 1024;
constexpr int ENC = 400;
constexpr int VOC = 32000;
constexpr int KRAW = EE + ENC;      // 912
constexpr int KIN  = 928;           // padded to /32
constexpr int G4   = 4 * HH;        // 4096
constexpr int MX   = TT * BB;       // 3200
constexpr int MO   = (TT - 1) * BB; // 3072

// ------------------------- scratch (static, no cudaMalloc) -----------------
__device__ float    g_X[MX * KIN];
__device__ float    g_Wp[G4 * KIN];          // permuted + padded W_ih
__device__ float    g_bias[G4];              // permuted b_ih + b_hh
__device__ float    g_Gin[(size_t)MX * G4];  // permuted input-proj gates
__device__ uint32_t g_WhhHi[G4 * HH];        // permuted tf32 split of W_hh
__device__ uint32_t g_WhhLo[G4 * HH];
__device__ float    g_h0[BB * HH];
__device__ float    g_h1[BB * HH];
__device__ float    g_c[BB * HH];
__device__ float    g_Hb[(size_t)MO * HH];

// ------------------------- helpers -----------------------------------------
__device__ __forceinline__ uint32_t f2tf(float x) {
    uint32_t u;
    asm("cvt.rna.tf32.f32 %0, %1;" : "=r"(u) : "f"(x));
    return u;
}

__device__ __forceinline__ void mma_tf32(float (&d)[4], const uint32_t (&a)[4],
                                         const uint32_t (&b)[2]) {
    asm volatile(
        "mma.sync.aligned.m16n8k8.row.col.f32.tf32.tf32.f32 "
        "{%0,%1,%2,%3},{%4,%5,%6,%7},{%8,%9},{%0,%1,%2,%3};"
        : "+f"(d[0]), "+f"(d[1]), "+f"(d[2]), "+f"(d[3])
        : "r"(a[0]), "r"(a[1]), "r"(a[2]), "r"(a[3]), "r"(b[0]), "r"(b[1]));
}

__device__ __forceinline__ void cpa16(void* s, const void* g) {
    uint32_t sa = (uint32_t)__cvta_generic_to_shared(s);
    asm volatile("cp.async.cg.shared.global [%0], [%1], 16;" ::"r"(sa), "l"(g));
}
__device__ __forceinline__ void cpa_commit() {
    asm volatile("cp.async.commit_group;");
}
template <int N> __device__ __forceinline__ void cpa_wait() {
    asm volatile("cp.async.wait_group %0;" ::"n"(N));
}

__device__ __forceinline__ float sigm(float x) { return 1.f / (1.f + expf(-x)); }

// ------------------------- pipelined NT tf32 GEMM ---------------------------
// C[M,N] = A[M,K] * B[N,K]^T, K % BK == 0, exact tiling. fp32 staged in SMEM
// via cp.async (S stages); tf32 round (+split) happens at fragment load.
// EPI 0: C[r*N+col] = acc + bias[col]
// EPI 2: out[(b*24+t)*VOC+col] = acc + bias[col], r = t*128+b
template <int BM, int BN, int BK, int WMS, int WNS, bool SPLIT, int EPI, int S>
__global__ void __launch_bounds__(WMS* WNS * 32)
gemm_nt_pipe(const float* __restrict__ A, const float* __restrict__ Bw,
             const float* __restrict__ bias, float* __restrict__ C,
             int M, int N, int K) {
    constexpr int THREADS = WMS * WNS * 32;
    constexpr int MF = BM / (WMS * 16);
    constexpr int NF = BN / (WNS * 8);
    constexpr int BKP = BK + 4;
    constexpr int KS = BK / 8;
    constexpr int ACH = BM * (BK / 4) / THREADS;
    constexpr int BCH = BN * (BK / 4) / THREADS;

    extern __shared__ float sm[];
    float* As = sm;                   // [S][BM][BKP]
    float* Bs = sm + S * BM * BKP;    // [S][BN][BKP]

    const int tid = threadIdx.x, lane = tid & 31, warp = tid >> 5;
    const int wm = warp % WMS, wn = warp / WMS;
    const int gq = lane >> 2, tq = lane & 3;
    const int m0 = blockIdx.y * BM, n0 = blockIdx.x * BN;
    const int KT = K / BK;

    auto loadA = [&](int st, int kt) {
#pragma unroll
        for (int it = 0; it < ACH; ++it) {
            int idx = tid + it * THREADS;
            int r = idx / (BK / 4), cq = idx % (BK / 4);
            cpa16(&As[(st * BM + r) * BKP + cq * 4],
                  &A[(size_t)(m0 + r) * K + kt * BK + cq * 4]);
        }
    };
    auto loadB = [&](int st, int kt) {
#pragma unroll
        for (int it = 0; it < BCH; ++it) {
            int idx = tid + it * THREADS;
            int r = idx / (BK / 4), cq = idx % (BK / 4);
            cpa16(&Bs[(st * BN + r) * BKP + cq * 4],
                  &Bw[(size_t)(n0 + r) * K + kt * BK + cq * 4]);
        }
    };

    float acc[MF][NF][4] = {};

    for (int s = 0; s < S - 1; ++s) { loadA(s, s); loadB(s, s); cpa_commit(); }

    for (int kt = 0; kt < KT; ++kt) {
        cpa_wait<S - 2>();
        __syncthreads();
        int nxt = kt + S - 1;
        if (nxt < KT) { int st = nxt % S; loadA(st, nxt); loadB(st, nxt); }
        cpa_commit();

        const float* Ast = &As[(kt % S) * BM * BKP];
        const float* Bst = &Bs[(kt % S) * BN * BKP];
#pragma unroll
        for (int ks = 0; ks < KS; ++ks) {
            uint32_t ah[MF][4], al[MF][4], bh[NF][2], bl[NF][2];
#pragma unroll
            for (int mi = 0; mi < MF; ++mi) {
                int row = wm * (MF * 16) + mi * 16;
#pragma unroll
                for (int q = 0; q < 4; ++q) {
                    int rr = row + gq + ((q & 1) ? 8 : 0);
                    int cc = ks * 8 + tq + ((q & 2) ? 4 : 0);
                    float v = Ast[rr * BKP + cc];
                    uint32_t hi = f2tf(v);
                    ah[mi][q] = hi;
                    if (SPLIT) al[mi][q] = f2tf(v - __uint_as_float(hi));
                }
            }
#pragma unroll
            for (int ni = 0; ni < NF; ++ni) {
                int col = wn * (NF * 8) + ni * 8;
#pragma unroll
                for (int q = 0; q < 2; ++q) {
                    float v = Bst[(col + gq) * BKP + ks * 8 + tq + (q ? 4 : 0)];
                    uint32_t hi = f2tf(v);
                    bh[ni][q] = hi;
                    if (SPLIT) bl[ni][q] = f2tf(v - __uint_as_float(hi));
                }
            }
#pragma unroll
            for (int mi = 0; mi < MF; ++mi)
#pragma unroll
                for (int ni = 0; ni < NF; ++ni) {
                    mma_tf32(acc[mi][ni], ah[mi], bh[ni]);
                    if (SPLIT) {
                        mma_tf32(acc[mi][ni], ah[mi], bl[ni]);
                        mma_tf32(acc[mi][ni], al[mi], bh[ni]);
                    }
                }
        }
    }
    cpa_wait<0>();

    // ---- epilogue ----
#pragma unroll
    for (int mi = 0; mi < MF; ++mi)
#pragma unroll
        for (int ni = 0; ni < NF; ++ni) {
            int row = m0 + wm * (MF * 16) + mi * 16 + gq;
            int col = n0 + wn * (NF * 8) + ni * 8 + tq * 2;
#pragma unroll
            for (int hf = 0; hf < 2; ++hf) {
                int r = row + hf * 8;
                float v0 = acc[mi][ni][hf * 2 + 0] + bias[col];
                float v1 = acc[mi][ni][hf * 2 + 1] + bias[col + 1];
                if constexpr (EPI == 0) {
                    *reinterpret_cast<float2*>(&C[(size_t)r * N + col]) =
                        make_float2(v0, v1);
                } else {
                    int b = r & (BB - 1);
                    int t = r >> 7;
                    size_t o = ((size_t)b * (TT - 1) + t) * VOC + col;
                    *reinterpret_cast<float2*>(&C[o]) = make_float2(v0, v1);
                }
            }
        }
}

// ------------------------- recurrence step (GEMM + fused cell) --------------
// gates = h_in @ W_hh^T (3-term tf32 split, W pre-split) + Gin[t]; then LSTM
// cell in epilogue. Gate dim is permuted: column p = 4*j + gate, so a BN=32
// tile owns 8 complete hidden units.
constexpr int RS = 3;
__global__ void __launch_bounds__(128)
rec_step(const float* __restrict__ hin, const uint32_t* __restrict__ WHi,
         const uint32_t* __restrict__ WLo, const float* __restrict__ GinT,
         float* __restrict__ c, float* __restrict__ hout,
         float* __restrict__ Hb, int t) {
    constexpr int BM = 128, BN = 32, BK = 32, BKP = 36, KT = HH / BK;
    constexpr int WMS = 2, WNS = 2;
    constexpr int MF = BM / (WMS * 16), NF = BN / (WNS * 8);  // 4, 2

    extern __shared__ float sm[];
    float* As = sm;                                        // [RS][128][36]
    uint32_t* Bh = (uint32_t*)(sm + RS * BM * BKP);        // [RS][32][36]
    uint32_t* Bl = Bh + RS * BN * BKP;
    __shared__ float Gt[BM][BN + 1];

    const int tid = threadIdx.x, lane = tid & 31, warp = tid >> 5;
    const int wm = warp % WMS, wn = warp / WMS;
    const int gq = lane >> 2, tq = lane & 3;
    const int n0 = blockIdx.x * BN;

    float acc[MF][NF][4] = {};

    if (t > 0) {
        auto loadA = [&](int st, int kt) {
#pragma unroll
            for (int it = 0; it < 8; ++it) {
                int idx = tid + it * 128;
                int r = idx / 8, cq = idx % 8;
                cpa16(&As[(st * BM + r) * BKP + cq * 4],
                      &hin[(size_t)r * HH + kt * BK + cq * 4]);
            }
        };
        auto loadB = [&](int st, int kt) {
#pragma unroll
            for (int it = 0; it < 2; ++it) {
                int idx = tid + it * 128;
                int r = idx / 8, cq = idx % 8;
                cpa16(&Bh[(st * BN + r) * BKP + cq * 4],
                      &WHi[(size_t)(n0 + r) * HH + kt * BK + cq * 4]);
                cpa16(&Bl[(st * BN + r) * BKP + cq * 4],
                      &WLo[(size_t)(n0 + r) * HH + kt * BK + cq * 4]);
            }
        };

        for (int s = 0; s < RS - 1; ++s) { loadA(s, s); loadB(s, s); cpa_commit(); }

        for (int kt = 0; kt < KT; ++kt) {
            cpa_wait<RS - 2>();
            __syncthreads();
            int nxt = kt + RS - 1;
            if (nxt < KT) { int st = nxt % RS; loadA(st, nxt); loadB(st, nxt); }
            cpa_commit();

            const float* Ast = &As[(kt % RS) * BM * BKP];
            const uint32_t* Bhs = &Bh[(kt % RS) * BN * BKP];
            const uint32_t* Bls = &Bl[(kt % RS) * BN * BKP];
#pragma unroll
            for (int ks = 0; ks < BK / 8; ++ks) {
                uint32_t ah[MF][4], al[MF][4], bhf[NF][2], blf[NF][2];
#pragma unroll
                for (int mi = 0; mi < MF; ++mi) {
                    int row = wm * (MF * 16) + mi * 16;
#pragma unroll
                    for (int q = 0; q < 4; ++q) {
                        int rr = row + gq + ((q & 1) ? 8 : 0);
                        int cc = ks * 8 + tq + ((q & 2) ? 4 : 0);
                        float v = Ast[rr * BKP + cc];
                        uint32_t hi = f2tf(v);
                        ah[mi][q] = hi;
                        al[mi][q] = f2tf(v - __uint_as_float(hi));
                    }
                }
#pragma unroll
                for (int ni = 0; ni < NF; ++ni) {
                    int col = wn * (NF * 8) + ni * 8;
#pragma unroll
                    for (int q = 0; q < 2; ++q) {
                        int off = (col + gq) * BKP + ks * 8 + tq + (q ? 4 : 0);
                        bhf[ni][q] = Bhs[off];
                        blf[ni][q] = Bls[off];
                    }
                }
#pragma unroll
                for (int mi = 0; mi < MF; ++mi)
#pragma unroll
                    for (int ni = 0; ni < NF; ++ni) {
                        mma_tf32(acc[mi][ni], ah[mi], bhf[ni]);
                        mma_tf32(acc[mi][ni], ah[mi], blf[ni]);
                        mma_tf32(acc[mi][ni], al[mi], bhf[ni]);
                    }
            }
        }
        cpa_wait<0>();
    }

    // ---- epilogue: gates -> SMEM (add Gin), then fused LSTM cell ----
#pragma unroll
    for (int mi = 0; mi < MF; ++mi)
#pragma unroll
        for (int ni = 0; ni < NF; ++ni)
#pragma unroll
            for (int hf = 0; hf < 2; ++hf) {
                int row = wm * (MF * 16) + mi * 16 + gq + hf * 8;
                int col = wn * (NF * 8) + ni * 8 + tq * 2;
                float2 ad = *reinterpret_cast<const float2*>(
                    &GinT[(size_t)row * G4 + n0 + col]);
                Gt[row][col]     = acc[mi][ni][hf * 2 + 0] + ad.x;
                Gt[row][col + 1] = acc[mi][ni][hf * 2 + 1] + ad.y;
            }
    __syncthreads();

    {
        int row = tid;                 // 128 threads == 128 batch rows
        int jbase = n0 >> 2;           // 8 hidden units per block
#pragma unroll
        for (int u = 0; u < 8; ++u) {
            float gi = Gt[row][u * 4 + 0];
            float gf = Gt[row][u * 4 + 1];
            float gg = Gt[row][u * 4 + 2];
            float go = Gt[row][u * 4 + 3];
            int ci = row * HH + jbase + u;
            float cn = sigm(gf) * c[ci] + sigm(gi) * tanhf(gg);
            float hn = sigm(go) * tanhf(cn);
            c[ci] = cn;
            hout[ci] = hn;
            if (t > 0) Hb[(size_t)(t - 1) * BB * HH + ci] = hn;
        }
    }
}

// ------------------------- prep kernels -------------------------------------
// permutation: output row p = 4*j + gate  <-  input row = gate*HH + j
__global__ void prep_bias_k(const float* __restrict__ bi,
                            const float* __restrict__ bh, float* out) {
    int p = blockIdx.x * blockDim.x + threadIdx.x;
    if (p >= G4) return;
    int src = (p & 3) * HH + (p >> 2);
    out[p] = bi[src] + bh[src];
}

__global__ void prep_W_k(const float* __restrict__ W, float* __restrict__ Wp) {
    int i = blockIdx.x * blockDim.x + threadIdx.x;
    if (i >= G4 * KIN) return;
    int p = i / KIN, k = i % KIN;
    int src = (p & 3) * HH + (p >> 2);
    Wp[i] = (k < KRAW) ? W[(size_t)src * KRAW + k] : 0.f;
}

__global__ void prep_Whh_k(const float* __restrict__ W, uint32_t* __restrict__ hi,
                           uint32_t* __restrict__ lo) {
    int i = blockIdx.x * blockDim.x + threadIdx.x;
    if (i >= G4 * HH) return;
    int p = i / HH, k = i % HH;
    int src = (p & 3) * HH + (p >> 2);
    float v = W[(size_t)src * HH + k];
    uint32_t h = f2tf(v);
    hi[i] = h;
    lo[i] = f2tf(v - __uint_as_float(h));
}

__global__ void prep_X_k(const float* __restrict__ feat,
                         const int* __restrict__ caps,
                         const float* __restrict__ emb, float* __restrict__ X) {
    int i = blockIdx.x * blockDim.x + threadIdx.x;
    if (i >= MX * KIN) return;
    int r = i / KIN, k = i % KIN;
    int t = r / BB, b = r % BB;
    float v;
    if (k < EE) {
        int tok = (t == 0) ? 1 : caps[b * TT + (t - 1)];
        v = emb[(size_t)tok * EE + k];
    } else if (k < KRAW) {
        v = feat[b * ENC + (k - EE)];
    } else {
        v = 0.f;
    }
    X[i] = v;
}

__global__ void zero_hc_k(float* h, float* c) {
    int i = blockIdx.x * blockDim.x + threadIdx.x;
    if (i < BB * HH) { h[i] = 0.f; c[i] = 0.f; }
}

// ------------------------- launch -------------------------------------------
extern "C" void kernel_launch(void* const* d_in, const int* in_sizes, int n_in,
                              void* d_out, int out_size) {
    const float* features = (const float*)d_in[0];
    const int*   captions = (const int*)d_in[1];
    const float* emb_W    = (const float*)d_in[2];
    const float* W_ih     = (const float*)d_in[3];
    const float* W_hh     = (const float*)d_in[4];
    const float* b_ih     = (const float*)d_in[5];
    const float* b_hh     = (const float*)d_in[6];
    // d_in[7..12]: attention weights — dead (softmax over a single element)
    const float* fcn_W    = (const float*)d_in[13];
    const float* fcn_b    = (const float*)d_in[14];
    float* out = (float*)d_out;

    float *X, *Wp, *bias, *Gin, *h0, *h1, *c, *Hb;
    uint32_t *WhhHi, *WhhLo;
    cudaGetSymbolAddress((void**)&X, g_X);
    cudaGetSymbolAddress((void**)&Wp, g_Wp);
    cudaGetSymbolAddress((void**)&bias, g_bias);
    cudaGetSymbolAddress((void**)&Gin, g_Gin);
    cudaGetSymbolAddress((void**)&WhhHi, g_WhhHi);
    cudaGetSymbolAddress((void**)&WhhLo, g_WhhLo);
    cudaGetSymbolAddress((void**)&h0, g_h0);
    cudaGetSymbolAddress((void**)&h1, g_h1);
    cudaGetSymbolAddress((void**)&c, g_c);
    cudaGetSymbolAddress((void**)&Hb, g_Hb);

    constexpr int SM_GEMM = 3 * (128 + 128) * 36 * (int)sizeof(float);  // 110592
    constexpr int SM_REC  = RS * 128 * 36 * 4 + 2 * RS * 32 * 36 * 4;   // 82944
    cudaFuncSetAttribute(gemm_nt_pipe<128, 128, 32, 2, 4, true, 0, 3>,
                         cudaFuncAttributeMaxDynamicSharedMemorySize, SM_GEMM);
    cudaFuncSetAttribute(gemm_nt_pipe<128, 128, 32, 2, 4, false, 2, 3>,
                         cudaFuncAttributeMaxDynamicSharedMemorySize, SM_GEMM);
    cudaFuncSetAttribute(rec_step,
                         cudaFuncAttributeMaxDynamicSharedMemorySize, SM_REC);

    // prep
    prep_bias_k<<<(G4 + 255) / 256, 256>>>(b_ih, b_hh, bias);
    prep_W_k<<<(G4 * KIN + 255) / 256, 256>>>(W_ih, Wp);
    prep_Whh_k<<<(G4 * HH + 255) / 256, 256>>>(W_hh, WhhHi, WhhLo);
    prep_X_k<<<(MX * KIN + 255) / 256, 256>>>(features, captions, emb_W, X);
    zero_hc_k<<<(BB * HH + 255) / 256, 256>>>(h0, c);

    // input projection for all timesteps (permuted gate layout, split tf32)
    gemm_nt_pipe<128, 128, 32, 2, 4, true, 0, 3>
        <<<dim3(G4 / 128, MX / 128), 256, SM_GEMM>>>(X, Wp, bias, Gin,
                                                     MX, G4, KIN);

    // sequential LSTM with fused cell; h double-buffered across steps
    float* hprev = h0;
    float* hcur  = h1;
    for (int t = 0; t < TT; t++) {
        rec_step<<<G4 / 32, 128, SM_REC>>>(hprev, WhhHi, WhhLo,
                                           Gin + (size_t)t * BB * G4, c, hcur,
                                           Hb, t);
        float* tmp = hprev; hprev = hcur; hcur = tmp;
    }

    // batched vocab projection (plain tf32)
    gemm_nt_pipe<128, 128, 32, 2, 4, false, 2, 3>
        <<<dim3(VOC / 128, MO / 128), 256, SM_GEMM>>>(Hb, fcn_W, fcn_b, out,
                                                      MO, VOC, HH);
}

// round 4
// speedup vs baseline: 1.3331x; 1.3331x over previous
#include <cuda_runtime.h>
#include <cstdint>

// ---------------------------------------------------------------------------
// DecoderRNNWithAttention — GB300 sm_103a, round 3
//  * attention is provably dead (softmax over 1 element) -> context==features
//  * input projection precomputed for all 25 steps (one GEMM, R1-style)
//  * vocab projection batched over 24 emitted steps (one GEMM, R1-style)
//  * gate-permuted layout (col p = 4*j+gate) -> LSTM cell fused into the
//    recurrence GEMM epilogue (25 launches instead of 50, no gates traffic)
//  * W_hh pre-split to tf32 hi/lo once per launch
// ---------------------------------------------------------------------------

constexpr int BB  = 128;
constexpr int TT  = 25;
constexpr int EE  = 512;
constexpr int HH  = 1024;
constexpr int ENC = 400;
constexpr int VOC = 32000;
constexpr int KRAW = EE + ENC;      // 912
constexpr int KIN  = 928;           // padded to /32
constexpr int G4   = 4 * HH;        // 4096
constexpr int MX   = TT * BB;       // 3200
constexpr int MO   = (TT - 1) * BB; // 3072

// ------------------------- scratch (static, no cudaMalloc) -----------------
__device__ float    g_X[MX * KIN];
__device__ float    g_Wp[G4 * KIN];          // permuted + padded W_ih
__device__ float    g_bias[G4];              // permuted b_ih + b_hh
__device__ float    g_Gin[(size_t)MX * G4];  // permuted input-proj gates
__device__ uint32_t g_WhhHi[G4 * HH];        // permuted tf32 split of W_hh
__device__ uint32_t g_WhhLo[G4 * HH];
__device__ float    g_h0[BB * HH];
__device__ float    g_h1[BB * HH];
__device__ float    g_c[BB * HH];
__device__ float    g_Hb[(size_t)MO * HH];

// ------------------------- helpers -----------------------------------------
__device__ __forceinline__ uint32_t f2tf(float x) {
    uint32_t u;
    asm("cvt.rna.tf32.f32 %0, %1;" : "=r"(u) : "f"(x));
    return u;
}

__device__ __forceinline__ void mma_tf32(float (&d)[4], const uint32_t (&a)[4],
                                         const uint32_t (&b)[2]) {
    asm volatile(
        "mma.sync.aligned.m16n8k8.row.col.f32.tf32.tf32.f32 "
        "{%0,%1,%2,%3},{%4,%5,%6,%7},{%8,%9},{%0,%1,%2,%3};"
        : "+f"(d[0]), "+f"(d[1]), "+f"(d[2]), "+f"(d[3])
        : "r"(a[0]), "r"(a[1]), "r"(a[2]), "r"(a[3]), "r"(b[0]), "r"(b[1]));
}

__device__ __forceinline__ float sigm(float x) { return 1.f / (1.f + expf(-x)); }

// ------------------------- generic NT tf32 GEMM (R1-proven) -----------------
// C[M,N] = A[M,K] * B[N,K]^T  (both K-contiguous), K % BK == 0, exact tiling.
// SPLIT: 3-term tf32 split for ~fp32 accuracy. Conversion at STS time.
// EPI 0: C = acc + bias[col]                      (row-major C, ld = N)
// EPI 2: out[(b*24 + t)*VOC + col] = acc + bias   (row = t*128 + b remap)
template <int BM, int BN, int BK, int WMS, int WNS, bool SPLIT, int EPI>
__global__ void __launch_bounds__(WMS * WNS * 32)
gemm_nt(const float* __restrict__ A, const float* __restrict__ Bw,
        const float* __restrict__ bias, float* __restrict__ C,
        int M, int N, int K) {
    constexpr int THREADS = WMS * WNS * 32;
    constexpr int MF = BM / (WMS * 16);
    constexpr int NF = BN / (WNS * 8);
    constexpr int LD = BK + 4;
    constexpr int NSP = SPLIT ? 2 : 1;
    constexpr int KS = BK / 8;
    constexpr int AIT = (BM * (BK / 4)) / THREADS;
    constexpr int BIT = (BN * (BK / 4)) / THREADS;

    __shared__ uint32_t As[NSP][BM][LD];
    __shared__ uint32_t Bs[NSP][BN][LD];

    const int tid  = threadIdx.x;
    const int lane = tid & 31;
    const int warp = tid >> 5;
    const int wm = warp % WMS;
    const int wn = warp / WMS;
    const int gq = lane >> 2;
    const int tq = lane & 3;
    const int m0 = blockIdx.y * BM;
    const int n0 = blockIdx.x * BN;

    float acc[MF][NF][4] = {};

    for (int kt = 0; kt < K; kt += BK) {
#pragma unroll
        for (int it = 0; it < AIT; it++) {
            int i = tid + it * THREADS;
            int r = i / (BK / 4);
            int c = (i % (BK / 4)) * 4;
            float4 v = *reinterpret_cast<const float4*>(
                &A[(size_t)(m0 + r) * K + kt + c]);
            float vv[4] = {v.x, v.y, v.z, v.w};
#pragma unroll
            for (int q = 0; q < 4; q++) {
                uint32_t hi = f2tf(vv[q]);
                As[0][r][c + q] = hi;
                if (SPLIT) As[1][r][c + q] = f2tf(vv[q] - __uint_as_float(hi));
            }
        }
#pragma unroll
        for (int it = 0; it < BIT; it++) {
            int i = tid + it * THREADS;
            int r = i / (BK / 4);
            int c = (i % (BK / 4)) * 4;
            float4 v = *reinterpret_cast<const float4*>(
                &Bw[(size_t)(n0 + r) * K + kt + c]);
            float vv[4] = {v.x, v.y, v.z, v.w};
#pragma unroll
            for (int q = 0; q < 4; q++) {
                uint32_t hi = f2tf(vv[q]);
                Bs[0][r][c + q] = hi;
                if (SPLIT) Bs[1][r][c + q] = f2tf(vv[q] - __uint_as_float(hi));
            }
        }
        __syncthreads();

#pragma unroll
        for (int ks = 0; ks < KS; ks++) {
            uint32_t af[NSP][MF][4];
            uint32_t bf[NSP][NF][2];
#pragma unroll
            for (int mi = 0; mi < MF; mi++) {
                int row = wm * (MF * 16) + mi * 16;
#pragma unroll
                for (int s = 0; s < NSP; s++) {
                    af[s][mi][0] = As[s][row + gq][ks * 8 + tq];
                    af[s][mi][1] = As[s][row + gq + 8][ks * 8 + tq];
                    af[s][mi][2] = As[s][row + gq][ks * 8 + tq + 4];
                    af[s][mi][3] = As[s][row + gq + 8][ks * 8 + tq + 4];
                }
            }
#pragma unroll
            for (int ni = 0; ni < NF; ni++) {
                int col = wn * (NF * 8) + ni * 8;
#pragma unroll
                for (int s = 0; s < NSP; s++) {
                    bf[s][ni][0] = Bs[s][col + gq][ks * 8 + tq];
                    bf[s][ni][1] = Bs[s][col + gq][ks * 8 + tq + 4];
                }
            }
#pragma unroll
            for (int mi = 0; mi < MF; mi++)
#pragma unroll
                for (int ni = 0; ni < NF; ni++) {
                    mma_tf32(acc[mi][ni], af[0][mi], bf[0][ni]);
                    if (SPLIT) {
                        mma_tf32(acc[mi][ni], af[0][mi], bf[1][ni]);
                        mma_tf32(acc[mi][ni], af[1][mi], bf[0][ni]);
                    }
                }
        }
        __syncthreads();
    }

    // ---- epilogue ----
#pragma unroll
    for (int mi = 0; mi < MF; mi++) {
#pragma unroll
        for (int ni = 0; ni < NF; ni++) {
            int row = m0 + wm * (MF * 16) + mi * 16 + gq;
            int col = n0 + wn * (NF * 8) + ni * 8 + tq * 2;
#pragma unroll
            for (int half = 0; half < 2; half++) {
                int r = row + half * 8;
                float v0 = acc[mi][ni][half * 2 + 0] + bias[col];
                float v1 = acc[mi][ni][half * 2 + 1] + bias[col + 1];
                if constexpr (EPI == 0) {
                    *reinterpret_cast<float2*>(&C[(size_t)r * N + col]) =
                        make_float2(v0, v1);
                } else {
                    int b  = r & (BB - 1);
                    int t  = r >> 7;
                    size_t o = ((size_t)b * (TT - 1) + t) * VOC + col;
                    *reinterpret_cast<float2*>(&C[o]) = make_float2(v0, v1);
                }
            }
        }
    }
}

// ------------------------- recurrence step (GEMM + fused cell) --------------
// gates = h_in @ W_hh^T (3-term tf32 split, W pre-split in global) + Gin[t];
// LSTM cell fused in the epilogue. Gate dim permuted: col p = 4*j + gate,
// so the BN=32 tile of one CTA owns 8 complete hidden units.
// R1-style internals: static SMEM, conversion at STS, no cp.async.
__global__ void __launch_bounds__(128)
rec_step(const float* __restrict__ hin, const uint32_t* __restrict__ WHi,
         const uint32_t* __restrict__ WLo, const float* __restrict__ GinT,
         float* __restrict__ c, float* __restrict__ hout,
         float* __restrict__ Hb, int t) {
    constexpr int BM = 128, BN = 32, BK = 16, LD = BK + 4;
    constexpr int WMS = 4;                       // 4 warps, wn == 0
    constexpr int MF = BM / (WMS * 16);          // 2
    constexpr int NF = BN / 8;                   // 4
    constexpr int KS = BK / 8;                   // 2

    __shared__ uint32_t Ah[BM][LD], Al[BM][LD];  // h tile, tf32 hi/lo
    __shared__ uint32_t Bh[BN][LD], Bl[BN][LD];  // W tile, pre-split
    __shared__ float Gt[BM][BN + 1];             // staged gates

    const int tid = threadIdx.x, lane = tid & 31, warp = tid >> 5;
    const int gq = lane >> 2, tq = lane & 3;
    const int n0 = blockIdx.x * BN;

    float acc[MF][NF][4] = {};

    if (t > 0) {
        for (int kt = 0; kt < HH; kt += BK) {
            // A tile: 128x16 fp32 -> hi/lo   (128 thr * 4 iters * float4)
#pragma unroll
            for (int it = 0; it < 4; ++it) {
                int i = tid + it * 128;
                int r = i / (BK / 4), cq = (i % (BK / 4)) * 4;
                float4 v = *reinterpret_cast<const float4*>(
                    &hin[(size_t)r * HH + kt + cq]);
                float vv[4] = {v.x, v.y, v.z, v.w};
#pragma unroll
                for (int q = 0; q < 4; q++) {
                    uint32_t hi = f2tf(vv[q]);
                    Ah[r][cq + q] = hi;
                    Al[r][cq + q] = f2tf(vv[q] - __uint_as_float(hi));
                }
            }
            // B tiles: raw uint4 copies (already tf32 bits)
            {
                int r = tid / (BK / 4), cq = (tid % (BK / 4)) * 4;
                *reinterpret_cast<uint4*>(&Bh[r][cq]) =
                    *reinterpret_cast<const uint4*>(
                        &WHi[(size_t)(n0 + r) * HH + kt + cq]);
                *reinterpret_cast<uint4*>(&Bl[r][cq]) =
                    *reinterpret_cast<const uint4*>(
                        &WLo[(size_t)(n0 + r) * HH + kt + cq]);
            }
            __syncthreads();

#pragma unroll
            for (int ks = 0; ks < KS; ++ks) {
                uint32_t ah[MF][4], al[MF][4], bh[NF][2], bl[NF][2];
#pragma unroll
                for (int mi = 0; mi < MF; ++mi) {
                    int row = warp * (MF * 16) + mi * 16;
                    ah[mi][0] = Ah[row + gq][ks * 8 + tq];
                    ah[mi][1] = Ah[row + gq + 8][ks * 8 + tq];
                    ah[mi][2] = Ah[row + gq][ks * 8 + tq + 4];
                    ah[mi][3] = Ah[row + gq + 8][ks * 8 + tq + 4];
                    al[mi][0] = Al[row + gq][ks * 8 + tq];
                    al[mi][1] = Al[row + gq + 8][ks * 8 + tq];
                    al[mi][2] = Al[row + gq][ks * 8 + tq + 4];
                    al[mi][3] = Al[row + gq + 8][ks * 8 + tq + 4];
                }
#pragma unroll
                for (int ni = 0; ni < NF; ++ni) {
                    int col = ni * 8;
                    bh[ni][0] = Bh[col + gq][ks * 8 + tq];
                    bh[ni][1] = Bh[col + gq][ks * 8 + tq + 4];
                    bl[ni][0] = Bl[col + gq][ks * 8 + tq];
                    bl[ni][1] = Bl[col + gq][ks * 8 + tq + 4];
                }
#pragma unroll
                for (int mi = 0; mi < MF; ++mi)
#pragma unroll
                    for (int ni = 0; ni < NF; ++ni) {
                        mma_tf32(acc[mi][ni], ah[mi], bh[ni]);
                        mma_tf32(acc[mi][ni], ah[mi], bl[ni]);
                        mma_tf32(acc[mi][ni], al[mi], bh[ni]);
                    }
            }
            __syncthreads();
        }
    }

    // ---- epilogue: stage gates (+Gin) to SMEM, then fused LSTM cell ----
#pragma unroll
    for (int mi = 0; mi < MF; ++mi)
#pragma unroll
        for (int ni = 0; ni < NF; ++ni)
#pragma unroll
            for (int hf = 0; hf < 2; ++hf) {
                int row = warp * (MF * 16) + mi * 16 + gq + hf * 8;
                int col = ni * 8 + tq * 2;
                float2 ad = *reinterpret_cast<const float2*>(
                    &GinT[(size_t)row * G4 + n0 + col]);
                Gt[row][col]     = acc[mi][ni][hf * 2 + 0] + ad.x;
                Gt[row][col + 1] = acc[mi][ni][hf * 2 + 1] + ad.y;
            }
    __syncthreads();

    {
        int row = tid;                 // 128 threads == 128 batch rows
        int jbase = n0 >> 2;           // this block owns hidden units jbase..+7
#pragma unroll
        for (int u = 0; u < 8; ++u) {
            float gi = Gt[row][u * 4 + 0];
            float gf = Gt[row][u * 4 + 1];
            float gg = Gt[row][u * 4 + 2];
            float go = Gt[row][u * 4 + 3];
            int ci = row * HH + jbase + u;
            float cn = sigm(gf) * c[ci] + sigm(gi) * tanhf(gg);
            float hn = sigm(go) * tanhf(cn);
            c[ci] = cn;
            hout[ci] = hn;
            if (t > 0) Hb[(size_t)(t - 1) * BB * HH + ci] = hn;
        }
    }
}

// ------------------------- prep kernels -------------------------------------
// permutation: output row p = 4*j + gate  <-  input row = gate*HH + j
__global__ void prep_bias_k(const float* __restrict__ bi,
                            const float* __restrict__ bh, float* out) {
    int p = blockIdx.x * blockDim.x + threadIdx.x;
    if (p >= G4) return;
    int src = (p & 3) * HH + (p >> 2);
    out[p] = bi[src] + bh[src];
}

__global__ void prep_W_k(const float* __restrict__ W, float* __restrict__ Wp) {
    int i = blockIdx.x * blockDim.x + threadIdx.x;
    if (i >= G4 * KIN) return;
    int p = i / KIN, k = i % KIN;
    int src = (p & 3) * HH + (p >> 2);
    Wp[i] = (k < KRAW) ? W[(size_t)src * KRAW + k] : 0.f;
}

__global__ void prep_Whh_k(const float* __restrict__ W, uint32_t* __restrict__ hi,
                           uint32_t* __restrict__ lo) {
    int i = blockIdx.x * blockDim.x + threadIdx.x;
    if (i >= G4 * HH) return;
    int p = i / HH, k = i % HH;
    int src = (p & 3) * HH + (p >> 2);
    float v = W[(size_t)src * HH + k];
    uint32_t h = f2tf(v);
    hi[i] = h;
    lo[i] = f2tf(v - __uint_as_float(h));
}

__global__ void prep_X_k(const float* __restrict__ feat,
                         const int* __restrict__ caps,
                         const float* __restrict__ emb, float* __restrict__ X) {
    int i = blockIdx.x * blockDim.x + threadIdx.x;
    if (i >= MX * KIN) return;
    int r = i / KIN, k = i % KIN;
    int t = r / BB, b = r % BB;
    float v;
    if (k < EE) {
        int tok = (t == 0) ? 1 : caps[b * TT + (t - 1)];
        v = emb[(size_t)tok * EE + k];
    } else if (k < KRAW) {
        v = feat[b * ENC + (k - EE)];
    } else {
        v = 0.f;
    }
    X[i] = v;
}

__global__ void zero_hc_k(float* h, float* c) {
    int i = blockIdx.x * blockDim.x + threadIdx.x;
    if (i < BB * HH) { h[i] = 0.f; c[i] = 0.f; }
}

// ------------------------- launch -------------------------------------------
extern "C" void kernel_launch(void* const* d_in, const int* in_sizes, int n_in,
                              void* d_out, int out_size) {
    const float* features = (const float*)d_in[0];
    const int*   captions = (const int*)d_in[1];
    const float* emb_W    = (const float*)d_in[2];
    const float* W_ih     = (const float*)d_in[3];
    const float* W_hh     = (const float*)d_in[4];
    const float* b_ih     = (const float*)d_in[5];
    const float* b_hh     = (const float*)d_in[6];
    // d_in[7..12]: attention weights — dead (softmax over a single element)
    const float* fcn_W    = (const float*)d_in[13];
    const float* fcn_b    = (const float*)d_in[14];
    float* out = (float*)d_out;

    float *X, *Wp, *bias, *Gin, *h0, *h1, *c, *Hb;
    uint32_t *WhhHi, *WhhLo;
    cudaGetSymbolAddress((void**)&X, g_X);
    cudaGetSymbolAddress((void**)&Wp, g_Wp);
    cudaGetSymbolAddress((void**)&bias, g_bias);
    cudaGetSymbolAddress((void**)&Gin, g_Gin);
    cudaGetSymbolAddress((void**)&WhhHi, g_WhhHi);
    cudaGetSymbolAddress((void**)&WhhLo, g_WhhLo);
    cudaGetSymbolAddress((void**)&h0, g_h0);
    cudaGetSymbolAddress((void**)&h1, g_h1);
    cudaGetSymbolAddress((void**)&c, g_c);
    cudaGetSymbolAddress((void**)&Hb, g_Hb);

    // prep
    prep_bias_k<<<(G4 + 255) / 256, 256>>>(b_ih, b_hh, bias);
    prep_W_k<<<(G4 * KIN + 255) / 256, 256>>>(W_ih, Wp);
    prep_Whh_k<<<(G4 * HH + 255) / 256, 256>>>(W_hh, WhhHi, WhhLo);
    prep_X_k<<<(MX * KIN + 255) / 256, 256>>>(features, captions, emb_W, X);
    zero_hc_k<<<(BB * HH + 255) / 256, 256>>>(h0, c);

    // input projection for all timesteps (permuted gate layout, split tf32)
    gemm_nt<128, 128, 16, 2, 4, true, 0>
        <<<dim3(G4 / 128, MX / 128), 256>>>(X, Wp, bias, Gin, MX, G4, KIN);

    // sequential LSTM, cell fused into GEMM epilogue; h double-buffered
    float* hprev = h0;
    float* hcur  = h1;
    for (int t = 0; t < TT; t++) {
        rec_step<<<G4 / 32, 128>>>(hprev, WhhHi, WhhLo,
                                   Gin + (size_t)t * BB * G4, c, hcur, Hb, t);
        float* tmp = hprev; hprev = hcur; hcur = tmp;
    }

    // batched vocab projection (plain tf32)
    gemm_nt<128, 128, 32, 2, 4, false, 2>
        <<<dim3(VOC / 128, MO / 128), 256>>>(Hb, fcn_W, fcn_b, out,
                                             MO, VOC, HH);
}

// round 5
// speedup vs baseline: 1.6101x; 1.2078x over previous
#include <cuda_runtime.h>
#include <cstdint>

// ---------------------------------------------------------------------------
// DecoderRNNWithAttention — GB300 sm_103a, round 4
//  * attention provably dead (softmax over 1 element) -> context == features
//  * input projection precomputed for all 25 steps (one GEMM, R1-style)
//  * vocab projection: 3-stage cp.async pipelined tf32 GEMM with ZERO
//    conversions in the hot loop (fcn_W pre-converted, Hb written as tf32
//    bits by the recurrence epilogue)
//  * recurrence: cell fused in epilogue; h emitted pre-split (tf32 hi/lo),
//    2-stage cp.async double buffer, 256 threads/CTA
// ---------------------------------------------------------------------------

constexpr int BB  = 128;
constexpr int TT  = 25;
constexpr int EE  = 512;
constexpr int HH  = 1024;
constexpr int ENC = 400;
constexpr int VOC = 32000;
constexpr int KRAW = EE + ENC;      // 912
constexpr int KIN  = 928;           // padded to /32
constexpr int G4   = 4 * HH;        // 4096
constexpr int MX   = TT * BB;       // 3200
constexpr int MO   = (TT - 1) * BB; // 3072

// ------------------------- scratch (static, no cudaMalloc) -----------------
__device__ float    g_X[MX * KIN];
__device__ float    g_Wp[G4 * KIN];            // permuted + padded W_ih
__device__ float    g_bias[G4];                // permuted b_ih + b_hh
__device__ float    g_Gin[(size_t)MX * G4];    // permuted input-proj gates
__device__ uint32_t g_WhhHi[G4 * HH];          // permuted tf32 split of W_hh
__device__ uint32_t g_WhhLo[G4 * HH];
__device__ uint32_t g_fcnWt[(size_t)VOC * HH]; // fcn_W as tf32 bits
__device__ uint32_t g_hHiA[BB * HH], g_hHiB[BB * HH];
__device__ uint32_t g_hLoA[BB * HH], g_hLoB[BB * HH];
__device__ float    g_c[BB * HH];
__device__ uint32_t g_Hb[(size_t)MO * HH];     // hidden states t=1..24, tf32 bits

// ------------------------- helpers -----------------------------------------
__device__ __forceinline__ uint32_t f2tf(float x) {
    uint32_t u;
    asm("cvt.rna.tf32.f32 %0, %1;" : "=r"(u) : "f"(x));
    return u;
}

__device__ __forceinline__ void mma_tf32(float (&d)[4], const uint32_t (&a)[4],
                                         const uint32_t (&b)[2]) {
    asm volatile(
        "mma.sync.aligned.m16n8k8.row.col.f32.tf32.tf32.f32 "
        "{%0,%1,%2,%3},{%4,%5,%6,%7},{%8,%9},{%0,%1,%2,%3};"
        : "+f"(d[0]), "+f"(d[1]), "+f"(d[2]), "+f"(d[3])
        : "r"(a[0]), "r"(a[1]), "r"(a[2]), "r"(a[3]), "r"(b[0]), "r"(b[1]));
}

__device__ __forceinline__ void cpa16(void* s, const void* g) {
    uint32_t sa = (uint32_t)__cvta_generic_to_shared(s);
    asm volatile("cp.async.cg.shared.global [%0], [%1], 16;" ::"r"(sa), "l"(g));
}
__device__ __forceinline__ void cpa_commit() {
    asm volatile("cp.async.commit_group;");
}
template <int N> __device__ __forceinline__ void cpa_wait() {
    asm volatile("cp.async.wait_group %0;" ::"n"(N));
}

__device__ __forceinline__ float sigm(float x) { return 1.f / (1.f + expf(-x)); }

// ------------------------- input GEMM (R1-proven, cvt at STS) ---------------
// Gin[r, p] = X[r,:] . Wp[p,:] + bias[p]   (3-term tf32 split)
template <int BM, int BN, int BK, int WMS, int WNS>
__global__ void __launch_bounds__(WMS * WNS * 32)
gemm_in(const float* __restrict__ A, const float* __restrict__ Bw,
        const float* __restrict__ bias, float* __restrict__ C,
        int M, int N, int K) {
    constexpr int THREADS = WMS * WNS * 32;
    constexpr int MF = BM / (WMS * 16);
    constexpr int NF = BN / (WNS * 8);
    constexpr int LD = BK + 4;
    constexpr int KS = BK / 8;
    constexpr int AIT = (BM * (BK / 4)) / THREADS;
    constexpr int BIT = (BN * (BK / 4)) / THREADS;

    __shared__ uint32_t As[2][BM][LD];
    __shared__ uint32_t Bs[2][BN][LD];

    const int tid  = threadIdx.x;
    const int lane = tid & 31;
    const int warp = tid >> 5;
    const int wm = warp % WMS;
    const int wn = warp / WMS;
    const int gq = lane >> 2;
    const int tq = lane & 3;
    const int m0 = blockIdx.y * BM;
    const int n0 = blockIdx.x * BN;

    float acc[MF][NF][4] = {};

    for (int kt = 0; kt < K; kt += BK) {
#pragma unroll
        for (int it = 0; it < AIT; it++) {
            int i = tid + it * THREADS;
            int r = i / (BK / 4);
            int c = (i % (BK / 4)) * 4;
            float4 v = *reinterpret_cast<const float4*>(
                &A[(size_t)(m0 + r) * K + kt + c]);
            float vv[4] = {v.x, v.y, v.z, v.w};
#pragma unroll
            for (int q = 0; q < 4; q++) {
                uint32_t hi = f2tf(vv[q]);
                As[0][r][c + q] = hi;
                As[1][r][c + q] = f2tf(vv[q] - __uint_as_float(hi));
            }
        }
#pragma unroll
        for (int it = 0; it < BIT; it++) {
            int i = tid + it * THREADS;
            int r = i / (BK / 4);
            int c = (i % (BK / 4)) * 4;
            float4 v = *reinterpret_cast<const float4*>(
                &Bw[(size_t)(n0 + r) * K + kt + c]);
            float vv[4] = {v.x, v.y, v.z, v.w};
#pragma unroll
            for (int q = 0; q < 4; q++) {
                uint32_t hi = f2tf(vv[q]);
                Bs[0][r][c + q] = hi;
                Bs[1][r][c + q] = f2tf(vv[q] - __uint_as_float(hi));
            }
        }
        __syncthreads();

#pragma unroll
        for (int ks = 0; ks < KS; ks++) {
            uint32_t af[2][MF][4];
            uint32_t bf[2][NF][2];
#pragma unroll
            for (int mi = 0; mi < MF; mi++) {
                int row = wm * (MF * 16) + mi * 16;
#pragma unroll
                for (int s = 0; s < 2; s++) {
                    af[s][mi][0] = As[s][row + gq][ks * 8 + tq];
                    af[s][mi][1] = As[s][row + gq + 8][ks * 8 + tq];
                    af[s][mi][2] = As[s][row + gq][ks * 8 + tq + 4];
                    af[s][mi][3] = As[s][row + gq + 8][ks * 8 + tq + 4];
                }
            }
#pragma unroll
            for (int ni = 0; ni < NF; ni++) {
                int col = wn * (NF * 8) + ni * 8;
#pragma unroll
                for (int s = 0; s < 2; s++) {
                    bf[s][ni][0] = Bs[s][col + gq][ks * 8 + tq];
                    bf[s][ni][1] = Bs[s][col + gq][ks * 8 + tq + 4];
                }
            }
#pragma unroll
            for (int mi = 0; mi < MF; mi++)
#pragma unroll
                for (int ni = 0; ni < NF; ni++) {
                    mma_tf32(acc[mi][ni], af[0][mi], bf[0][ni]);
                    mma_tf32(acc[mi][ni], af[0][mi], bf[1][ni]);
                    mma_tf32(acc[mi][ni], af[1][mi], bf[0][ni]);
                }
        }
        __syncthreads();
    }

#pragma unroll
    for (int mi = 0; mi < MF; mi++)
#pragma unroll
        for (int ni = 0; ni < NF; ni++) {
            int row = m0 + wm * (MF * 16) + mi * 16 + gq;
            int col = n0 + wn * (NF * 8) + ni * 8 + tq * 2;
#pragma unroll
            for (int half = 0; half < 2; half++) {
                int r = row + half * 8;
                float v0 = acc[mi][ni][half * 2 + 0] + bias[col];
                float v1 = acc[mi][ni][half * 2 + 1] + bias[col + 1];
                *reinterpret_cast<float2*>(&C[(size_t)r * N + col]) =
                    make_float2(v0, v1);
            }
        }
}

// ------------------------- vocab GEMM: pipelined, cvt-free ------------------
// out[(b*24+t)*VOC+col] = Hb[r,:] . fcnWt[col,:] + fcn_b[col], r = t*128+b.
// A and B are already tf32 bits; 3-stage cp.async; inner loop = LDS + MMA.
constexpr int VS = 3;
__global__ void __launch_bounds__(256)
gemm_vocab(const uint32_t* __restrict__ A, const uint32_t* __restrict__ Bw,
           const float* __restrict__ bias, float* __restrict__ C) {
    constexpr int BM = 128, BN = 128, BK = 32, LD = BK + 4;
    constexpr int WMS = 2, WNS = 4;
    constexpr int MF = 4, NF = 4, KS = 4;
    constexpr int KT = HH / BK;          // 32

    extern __shared__ uint32_t sv[];
    uint32_t* As = sv;                   // [VS][BM][LD]
    uint32_t* Bs = sv + VS * BM * LD;    // [VS][BN][LD]

    const int tid = threadIdx.x, lane = tid & 31, warp = tid >> 5;
    const int wm = warp % WMS, wn = warp / WMS;
    const int gq = lane >> 2, tq = lane & 3;
    const int m0 = blockIdx.y * BM, n0 = blockIdx.x * BN;

    auto loadT = [&](int st, int kt) {
#pragma unroll
        for (int it = 0; it < 4; ++it) {          // A: 128 rows x 8 chunks
            int i = tid + it * 256;
            int r = i >> 3, cq = (i & 7) * 4;
            cpa16(&As[(st * BM + r) * LD + cq],
                  &A[(size_t)(m0 + r) * HH + kt * BK + cq]);
        }
#pragma unroll
        for (int it = 0; it < 4; ++it) {          // B: 128 rows x 8 chunks
            int i = tid + it * 256;
            int r = i >> 3, cq = (i & 7) * 4;
            cpa16(&Bs[(st * BN + r) * LD + cq],
                  &Bw[(size_t)(n0 + r) * HH + kt * BK + cq]);
        }
    };

    float acc[MF][NF][4] = {};

    loadT(0, 0); cpa_commit();
    loadT(1, 1); cpa_commit();

    for (int kt = 0; kt < KT; ++kt) {
        cpa_wait<1>();
        __syncthreads();
        if (kt + 2 < KT) loadT((kt + 2) % VS, kt + 2);
        cpa_commit();

        const uint32_t* Ast = &As[(kt % VS) * BM * LD];
        const uint32_t* Bst = &Bs[(kt % VS) * BN * LD];
#pragma unroll
        for (int ks = 0; ks < KS; ++ks) {
            uint32_t af[MF][4], bf[NF][2];
#pragma unroll
            for (int mi = 0; mi < MF; ++mi) {
                int row = wm * (MF * 16) + mi * 16;
                af[mi][0] = Ast[(row + gq) * LD + ks * 8 + tq];
                af[mi][1] = Ast[(row + gq + 8) * LD + ks * 8 + tq];
                af[mi][2] = Ast[(row + gq) * LD + ks * 8 + tq + 4];
                af[mi][3] = Ast[(row + gq + 8) * LD + ks * 8 + tq + 4];
            }
#pragma unroll
            for (int ni = 0; ni < NF; ++ni) {
                int col = wn * (NF * 8) + ni * 8;
                bf[ni][0] = Bst[(col + gq) * LD + ks * 8 + tq];
                bf[ni][1] = Bst[(col + gq) * LD + ks * 8 + tq + 4];
            }
#pragma unroll
            for (int mi = 0; mi < MF; ++mi)
#pragma unroll
                for (int ni = 0; ni < NF; ++ni)
                    mma_tf32(acc[mi][ni], af[mi], bf[ni]);
        }
    }
    cpa_wait<0>();

#pragma unroll
    for (int mi = 0; mi < MF; ++mi)
#pragma unroll
        for (int ni = 0; ni < NF; ++ni) {
            int row = m0 + wm * (MF * 16) + mi * 16 + gq;
            int col = n0 + wn * (NF * 8) + ni * 8 + tq * 2;
#pragma unroll
            for (int hf = 0; hf < 2; ++hf) {
                int r = row + hf * 8;
                float v0 = acc[mi][ni][hf * 2 + 0] + bias[col];
                float v1 = acc[mi][ni][hf * 2 + 1] + bias[col + 1];
                int b = r & (BB - 1);
                int t = r >> 7;
                size_t o = ((size_t)b * (TT - 1) + t) * VOC + col;
                *reinterpret_cast<float2*>(&C[o]) = make_float2(v0, v1);
            }
        }
}

// ------------------------- recurrence step (pipelined, cvt-free) ------------
// gates = h @ W_hh^T (3-term split, everything pre-split as tf32 bits) +
// Gin[t]; fused LSTM cell; emits h pre-split (hi/lo) + Hb (tf32 bits).
// Gate dim permuted: col p = 4*j + gate. 128 CTAs x 256 threads.
__global__ void __launch_bounds__(256)
rec_step(const uint32_t* __restrict__ hHi, const uint32_t* __restrict__ hLo,
         const uint32_t* __restrict__ WHi, const uint32_t* __restrict__ WLo,
         const float* __restrict__ GinT, float* __restrict__ c,
         uint32_t* __restrict__ hHiO, uint32_t* __restrict__ hLoO,
         uint32_t* __restrict__ Hb, int t) {
    constexpr int BM = 128, BN = 32, BK = 32, LD = BK + 4;
    constexpr int WMS = 4, WNS = 2;
    constexpr int MF = 2, NF = 2, KS = 4;
    constexpr int KT = HH / BK;   // 32
    constexpr int AW = BM * LD;   // words per A stage (4608)
    constexpr int BW = BN * LD;   // words per B stage (1152)

    extern __shared__ uint32_t sr[];
    uint32_t* AHi = sr;                    // [2][BM][LD]
    uint32_t* ALo = sr + 2 * AW;
    uint32_t* BHi = sr + 4 * AW;           // [2][BN][LD]
    uint32_t* BLo = sr + 4 * AW + 2 * BW;
    __shared__ float Gt[BM][BN + 1];

    const int tid = threadIdx.x, lane = tid & 31, warp = tid >> 5;
    const int wm = warp % WMS, wn = warp / WMS;
    const int gq = lane >> 2, tq = lane & 3;
    const int n0 = blockIdx.x * BN;

    float acc[MF][NF][4] = {};

    if (t > 0) {
        auto loadT = [&](int st, int kt) {
#pragma unroll
            for (int it = 0; it < 4; ++it) {       // A: 128 x 8 chunks
                int i = tid + it * 256;
                int r = i >> 3, cq = (i & 7) * 4;
                cpa16(&AHi[st * AW + r * LD + cq],
                      &hHi[(size_t)r * HH + kt * BK + cq]);
                cpa16(&ALo[st * AW + r * LD + cq],
                      &hLo[(size_t)r * HH + kt * BK + cq]);
            }
            {                                       // B: 32 x 8 chunks
                int r = tid >> 3, cq = (tid & 7) * 4;
                cpa16(&BHi[st * BW + r * LD + cq],
                      &WHi[(size_t)(n0 + r) * HH + kt * BK + cq]);
                cpa16(&BLo[st * BW + r * LD + cq],
                      &WLo[(size_t)(n0 + r) * HH + kt * BK + cq]);
            }
        };

        loadT(0, 0); cpa_commit();

        for (int kt = 0; kt < KT; ++kt) {
            cpa_wait<0>();
            __syncthreads();
            if (kt + 1 < KT) loadT((kt + 1) & 1, kt + 1);
            cpa_commit();

            const uint32_t* Ah = &AHi[(kt & 1) * AW];
            const uint32_t* Al = &ALo[(kt & 1) * AW];
            const uint32_t* Bh = &BHi[(kt & 1) * BW];
            const uint32_t* Bl = &BLo[(kt & 1) * BW];
#pragma unroll
            for (int ks = 0; ks < KS; ++ks) {
                uint32_t ah[MF][4], al[MF][4], bh[NF][2], bl[NF][2];
#pragma unroll
                for (int mi = 0; mi < MF; ++mi) {
                    int row = wm * (MF * 16) + mi * 16;
                    ah[mi][0] = Ah[(row + gq) * LD + ks * 8 + tq];
                    ah[mi][1] = Ah[(row + gq + 8) * LD + ks * 8 + tq];
                    ah[mi][2] = Ah[(row + gq) * LD + ks * 8 + tq + 4];
                    ah[mi][3] = Ah[(row + gq + 8) * LD + ks * 8 + tq + 4];
                    al[mi][0] = Al[(row + gq) * LD + ks * 8 + tq];
                    al[mi][1] = Al[(row + gq + 8) * LD + ks * 8 + tq];
                    al[mi][2] = Al[(row + gq) * LD + ks * 8 + tq + 4];
                    al[mi][3] = Al[(row + gq + 8) * LD + ks * 8 + tq + 4];
                }
#pragma unroll
                for (int ni = 0; ni < NF; ++ni) {
                    int col = wn * (NF * 8) + ni * 8;
                    bh[ni][0] = Bh[(col + gq) * LD + ks * 8 + tq];
                    bh[ni][1] = Bh[(col + gq) * LD + ks * 8 + tq + 4];
                    bl[ni][0] = Bl[(col + gq) * LD + ks * 8 + tq];
                    bl[ni][1] = Bl[(col + gq) * LD + ks * 8 + tq + 4];
                }
#pragma unroll
                for (int mi = 0; mi < MF; ++mi)
#pragma unroll
                    for (int ni = 0; ni < NF; ++ni) {
                        mma_tf32(acc[mi][ni], ah[mi], bh[ni]);
                        mma_tf32(acc[mi][ni], ah[mi], bl[ni]);
                        mma_tf32(acc[mi][ni], al[mi], bh[ni]);
                    }
            }
        }
        cpa_wait<0>();
    }

    // ---- epilogue: stage gates (+Gin) to SMEM, then fused LSTM cell ----
#pragma unroll
    for (int mi = 0; mi < MF; ++mi)
#pragma unroll
        for (int ni = 0; ni < NF; ++ni)
#pragma unroll
            for (int hf = 0; hf < 2; ++hf) {
                int row = wm * (MF * 16) + mi * 16 + gq + hf * 8;
                int col = wn * (NF * 8) + ni * 8 + tq * 2;
                float2 ad = *reinterpret_cast<const float2*>(
                    &GinT[(size_t)row * G4 + n0 + col]);
                Gt[row][col]     = acc[mi][ni][hf * 2 + 0] + ad.x;
                Gt[row][col + 1] = acc[mi][ni][hf * 2 + 1] + ad.y;
            }
    __syncthreads();

    if (tid < BM) {
        int row = tid;
        int jbase = n0 >> 2;
#pragma unroll
        for (int u = 0; u < 8; ++u) {
            float gi = Gt[row][u * 4 + 0];
            float gf = Gt[row][u * 4 + 1];
            float gg = Gt[row][u * 4 + 2];
            float go = Gt[row][u * 4 + 3];
            int ci = row * HH + jbase + u;
            float cn = sigm(gf) * c[ci] + sigm(gi) * tanhf(gg);
            float hn = sigm(go) * tanhf(cn);
            c[ci] = cn;
            uint32_t hi = f2tf(hn);
            hHiO[ci] = hi;
            hLoO[ci] = f2tf(hn - __uint_as_float(hi));
            if (t > 0) Hb[(size_t)(t - 1) * BB * HH + ci] = hi;
        }
    }
}

// ------------------------- prep kernels -------------------------------------
// permutation: output row p = 4*j + gate  <-  input row = gate*HH + j
__global__ void prep_bias_k(const float* __restrict__ bi,
                            const float* __restrict__ bh, float* out) {
    int p = blockIdx.x * blockDim.x + threadIdx.x;
    if (p >= G4) return;
    int src = (p & 3) * HH + (p >> 2);
    out[p] = bi[src] + bh[src];
}

__global__ void prep_W_k(const float* __restrict__ W, float* __restrict__ Wp) {
    int i = blockIdx.x * blockDim.x + threadIdx.x;
    if (i >= G4 * KIN) return;
    int p = i / KIN, k = i % KIN;
    int src = (p & 3) * HH + (p >> 2);
    Wp[i] = (k < KRAW) ? W[(size_t)src * KRAW + k] : 0.f;
}

__global__ void prep_Whh_k(const float* __restrict__ W,
                           uint32_t* __restrict__ hi,
                           uint32_t* __restrict__ lo) {
    int i = blockIdx.x * blockDim.x + threadIdx.x;
    if (i >= G4 * HH) return;
    int p = i / HH, k = i % HH;
    int src = (p & 3) * HH + (p >> 2);
    float v = W[(size_t)src * HH + k];
    uint32_t h = f2tf(v);
    hi[i] = h;
    lo[i] = f2tf(v - __uint_as_float(h));
}

__global__ void prep_fcnW_k(const float* __restrict__ W,
                            uint32_t* __restrict__ Wt) {
    size_t i = (size_t)blockIdx.x * blockDim.x + threadIdx.x;  // quad index
    if (i * 4 >= (size_t)VOC * HH) return;
    float4 v = *reinterpret_cast<const float4*>(&W[i * 4]);
    uint4 o;
    o.x = f2tf(v.x); o.y = f2tf(v.y); o.z = f2tf(v.z); o.w = f2tf(v.w);
    *reinterpret_cast<uint4*>(&Wt[i * 4]) = o;
}

__global__ void prep_X_k(const float* __restrict__ feat,
                         const int* __restrict__ caps,
                         const float* __restrict__ emb, float* __restrict__ X) {
    int i = blockIdx.x * blockDim.x + threadIdx.x;
    if (i >= MX * KIN) return;
    int r = i / KIN, k = i % KIN;
    int t = r / BB, b = r % BB;
    float v;
    if (k < EE) {
        int tok = (t == 0) ? 1 : caps[b * TT + (t - 1)];
        v = emb[(size_t)tok * EE + k];
    } else if (k < KRAW) {
        v = feat[b * ENC + (k - EE)];
    } else {
        v = 0.f;
    }
    X[i] = v;
}

__global__ void zero_init_k(uint32_t* hi, uint32_t* lo, float* c) {
    int i = blockIdx.x * blockDim.x + threadIdx.x;
    if (i < BB * HH) { hi[i] = 0u; lo[i] = 0u; c[i] = 0.f; }
}

// ------------------------- launch -------------------------------------------
extern "C" void kernel_launch(void* const* d_in, const int* in_sizes, int n_in,
                              void* d_out, int out_size) {
    const float* features = (const float*)d_in[0];
    const int*   captions = (const int*)d_in[1];
    const float* emb_W    = (const float*)d_in[2];
    const float* W_ih     = (const float*)d_in[3];
    const float* W_hh     = (const float*)d_in[4];
    const float* b_ih     = (const float*)d_in[5];
    const float* b_hh     = (const float*)d_in[6];
    // d_in[7..12]: attention weights — dead (softmax over a single element)
    const float* fcn_W    = (const float*)d_in[13];
    const float* fcn_b    = (const float*)d_in[14];
    float* out = (float*)d_out;

    float *X, *Wp, *bias, *Gin, *c;
    uint32_t *WhhHi, *WhhLo, *fcnWt, *hHiA, *hHiB, *hLoA, *hLoB, *Hb;
    cudaGetSymbolAddress((void**)&X, g_X);
    cudaGetSymbolAddress((void**)&Wp, g_Wp);
    cudaGetSymbolAddress((void**)&bias, g_bias);
    cudaGetSymbolAddress((void**)&Gin, g_Gin);
    cudaGetSymbolAddress((void**)&WhhHi, g_WhhHi);
    cudaGetSymbolAddress((void**)&WhhLo, g_WhhLo);
    cudaGetSymbolAddress((void**)&fcnWt, g_fcnWt);
    cudaGetSymbolAddress((void**)&hHiA, g_hHiA);
    cudaGetSymbolAddress((void**)&hHiB, g_hHiB);
    cudaGetSymbolAddress((void**)&hLoA, g_hLoA);
    cudaGetSymbolAddress((void**)&hLoB, g_hLoB);
    cudaGetSymbolAddress((void**)&c, g_c);
    cudaGetSymbolAddress((void**)&Hb, g_Hb);

    constexpr int SM_VOC = VS * (128 + 128) * 36 * (int)sizeof(uint32_t); // 110592
    constexpr int SM_REC = (4 * 128 * 36 + 4 * 32 * 36) * (int)sizeof(uint32_t); // 92160
    cudaFuncSetAttribute(gemm_vocab,
                         cudaFuncAttributeMaxDynamicSharedMemorySize, SM_VOC);
    cudaFuncSetAttribute(rec_step,
                         cudaFuncAttributeMaxDynamicSharedMemorySize, SM_REC);

    // prep
    prep_bias_k<<<(G4 + 255) / 256, 256>>>(b_ih, b_hh, bias);
    prep_W_k<<<(G4 * KIN + 255) / 256, 256>>>(W_ih, Wp);
    prep_Whh_k<<<(G4 * HH + 255) / 256, 256>>>(W_hh, WhhHi, WhhLo);
    prep_fcnW_k<<<(VOC * HH / 4 + 255) / 256, 256>>>(fcn_W, fcnWt);
    prep_X_k<<<(MX * KIN + 255) / 256, 256>>>(features, captions, emb_W, X);
    zero_init_k<<<(BB * HH + 255) / 256, 256>>>(hHiA, hLoA, c);

    // input projection for all timesteps (permuted gate layout, split tf32)
    gemm_in<128, 128, 16, 2, 4>
        <<<dim3(G4 / 128, MX / 128), 256>>>(X, Wp, bias, Gin, MX, G4, KIN);

    // sequential LSTM, cell fused; h kept pre-split, double-buffered
    uint32_t *hiP = hHiA, *loP = hLoA, *hiC = hHiB, *loC = hLoB;
    for (int t = 0; t < TT; t++) {
        rec_step<<<G4 / 32, 256, SM_REC>>>(hiP, loP, WhhHi, WhhLo,
                                           Gin + (size_t)t * BB * G4, c,
                                           hiC, loC, Hb, t);
        uint32_t* tm;
        tm = hiP; hiP = hiC; hiC = tm;
        tm = loP; loP = loC; loC = tm;
    }

    // batched vocab projection (plain tf32, pipelined, cvt-free)
    gemm_vocab<<<dim3(VOC / 128, MO / 128), 256, SM_VOC>>>(Hb, fcnWt, fcn_b,
                                                           out);
}

// round 6
// speedup vs baseline: 1.9978x; 1.2408x over previous
#include <cuda_runtime.h>
#include <cuda_bf16.h>
#include <cstdint>

// ---------------------------------------------------------------------------
// DecoderRNNWithAttention — GB300 sm_103a, round 5
//  * attention provably dead (softmax over 1 element) -> context == features
//  * input projection + recurrence: 3-term bf16 split (m16n8k16), cvt-free
//    pipelined (operands pre-split into packed bf16x2 in prep kernels)
//  * vocab projection: plain-tf32 cvt-free pipeline, grid swapped so m-tiles
//    vary fastest -> fcn_W read from DRAM once (L2 reuse), not 24x
// ---------------------------------------------------------------------------

constexpr int BB  = 128;
constexpr int TT  = 25;
constexpr int EE  = 512;
constexpr int HH  = 1024;
constexpr int ENC = 400;
constexpr int VOC = 32000;
constexpr int KRAW = EE + ENC;      // 912
constexpr int KIN  = 928;           // padded to /32
constexpr int KINP = KIN / 2;       // 464 bf16 pairs
constexpr int HHP  = HH / 2;        // 512 bf16 pairs
constexpr int G4   = 4 * HH;        // 4096
constexpr int MX   = TT * BB;       // 3200
constexpr int MO   = (TT - 1) * BB; // 3072

// ------------------------- scratch (static, no cudaMalloc) -----------------
__device__ uint32_t g_Xhi[MX * KINP];            // bf16x2 pairs
__device__ uint32_t g_Xlo[MX * KINP];
__device__ uint32_t g_WihHi[G4 * KINP];          // permuted + padded
__device__ uint32_t g_WihLo[G4 * KINP];
__device__ float    g_bias[G4];                  // permuted b_ih + b_hh
__device__ float    g_Gin[(size_t)MX * G4];      // permuted input-proj gates
__device__ uint32_t g_WhhHi[G4 * HHP];           // permuted bf16x2 split
__device__ uint32_t g_WhhLo[G4 * HHP];
__device__ uint32_t g_fcnWt[(size_t)VOC * HH];   // fcn_W as tf32 bits
__device__ uint32_t g_hHiA[BB * HHP], g_hHiB[BB * HHP];   // h as bf16x2
__device__ uint32_t g_hLoA[BB * HHP], g_hLoB[BB * HHP];
__device__ float    g_c[BB * HH];
__device__ uint32_t g_Hb[(size_t)MO * HH];       // hidden states, tf32 bits

// ------------------------- helpers -----------------------------------------
__device__ __forceinline__ uint32_t f2tf(float x) {
    uint32_t u;
    asm("cvt.rna.tf32.f32 %0, %1;" : "=r"(u) : "f"(x));
    return u;
}

__device__ __forceinline__ uint32_t pack_bf(float a, float b) {
    __nv_bfloat162 t = __floats2bfloat162_rn(a, b);  // .x=a (low), .y=b (high)
    return *reinterpret_cast<uint32_t*>(&t);
}

__device__ __forceinline__ void mma_tf32(float (&d)[4], const uint32_t (&a)[4],
                                         const uint32_t (&b)[2]) {
    asm volatile(
        "mma.sync.aligned.m16n8k8.row.col.f32.tf32.tf32.f32 "
        "{%0,%1,%2,%3},{%4,%5,%6,%7},{%8,%9},{%0,%1,%2,%3};"
        : "+f"(d[0]), "+f"(d[1]), "+f"(d[2]), "+f"(d[3])
        : "r"(a[0]), "r"(a[1]), "r"(a[2]), "r"(a[3]), "r"(b[0]), "r"(b[1]));
}

__device__ __forceinline__ void mma_bf16(float (&d)[4], const uint32_t (&a)[4],
                                         const uint32_t (&b)[2]) {
    asm volatile(
        "mma.sync.aligned.m16n8k16.row.col.f32.bf16.bf16.f32 "
        "{%0,%1,%2,%3},{%4,%5,%6,%7},{%8,%9},{%0,%1,%2,%3};"
        : "+f"(d[0]), "+f"(d[1]), "+f"(d[2]), "+f"(d[3])
        : "r"(a[0]), "r"(a[1]), "r"(a[2]), "r"(a[3]), "r"(b[0]), "r"(b[1]));
}

__device__ __forceinline__ void cpa16(void* s, const void* g) {
    uint32_t sa = (uint32_t)__cvta_generic_to_shared(s);
    asm volatile("cp.async.cg.shared.global [%0], [%1], 16;" ::"r"(sa), "l"(g));
}
__device__ __forceinline__ void cpa_commit() {
    asm volatile("cp.async.commit_group;");
}
template <int N> __device__ __forceinline__ void cpa_wait() {
    asm volatile("cp.async.wait_group %0;" ::"n"(N));
}

__device__ __forceinline__ float sigm(float x) { return 1.f / (1.f + expf(-x)); }

// ------------------------- input GEMM: bf16 3-term split, pipelined ---------
// Gin[r, p] = X[r,:] . Wih[p,:] + bias[p].  A/B pre-split bf16x2 pairs.
// BM=128 BN=128 BK=32 (16 pairs), 2-stage cp.async double buffer, 256 thr.
__global__ void __launch_bounds__(256)
gemm_in(const uint32_t* __restrict__ Ahi, const uint32_t* __restrict__ Alo,
        const uint32_t* __restrict__ Bhi, const uint32_t* __restrict__ Blo,
        const float* __restrict__ bias, float* __restrict__ C) {
    constexpr int BM = 128, BN = 128, LDP = 20;     // 16 pairs + 4 pad
    constexpr int WMS = 2, WNS = 4;
    constexpr int MF = 4, NF = 4, KS = 2;           // 2 k-slices of 16
    constexpr int KT = KIN / 32;                    // 29
    constexpr int ASW = BM * LDP;                   // 2560 words per stage
    constexpr int BSW = BN * LDP;

    extern __shared__ uint32_t sm[];
    uint32_t* AHs = sm;                  // [2][ASW]
    uint32_t* ALs = sm + 2 * ASW;
    uint32_t* BHs = sm + 4 * ASW;        // [2][BSW]
    uint32_t* BLs = sm + 4 * ASW + 2 * BSW;

    const int tid = threadIdx.x, lane = tid & 31, warp = tid >> 5;
    const int wm = warp % WMS, wn = warp / WMS;
    const int gq = lane >> 2, tq = lane & 3;
    const int m0 = blockIdx.y * BM, n0 = blockIdx.x * BN;

    auto loadT = [&](int st, int kt) {
#pragma unroll
        for (int it = 0; it < 2; ++it) {     // 512 chunk-ids: r 0..127, cq 0..12
            int i = tid + it * 256;
            int r = i >> 2, cq = (i & 3) * 4;
            cpa16(&AHs[st * ASW + r * LDP + cq],
                  &Ahi[(size_t)(m0 + r) * KINP + kt * 16 + cq]);
            cpa16(&ALs[st * ASW + r * LDP + cq],
                  &Alo[(size_t)(m0 + r) * KINP + kt * 16 + cq]);
            cpa16(&BHs[st * BSW + r * LDP + cq],
                  &Bhi[(size_t)(n0 + r) * KINP + kt * 16 + cq]);
            cpa16(&BLs[st * BSW + r * LDP + cq],
                  &Blo[(size_t)(n0 + r) * KINP + kt * 16 + cq]);
        }
    };

    float acc[MF][NF][4] = {};

    loadT(0, 0); cpa_commit();

    for (int kt = 0; kt < KT; ++kt) {
        cpa_wait<0>();
        __syncthreads();
        if (kt + 1 < KT) loadT((kt + 1) & 1, kt + 1);
        cpa_commit();

        const uint32_t* Ah = &AHs[(kt & 1) * ASW];
        const uint32_t* Al = &ALs[(kt & 1) * ASW];
        const uint32_t* Bh = &BHs[(kt & 1) * BSW];
        const uint32_t* Bl = &BLs[(kt & 1) * BSW];
#pragma unroll
        for (int ks = 0; ks < KS; ++ks) {
            uint32_t ah[MF][4], al[MF][4], bh[NF][2], bl[NF][2];
#pragma unroll
            for (int mi = 0; mi < MF; ++mi) {
                int row = wm * (MF * 16) + mi * 16;
                ah[mi][0] = Ah[(row + gq) * LDP + ks * 8 + tq];
                ah[mi][1] = Ah[(row + gq + 8) * LDP + ks * 8 + tq];
                ah[mi][2] = Ah[(row + gq) * LDP + ks * 8 + tq + 4];
                ah[mi][3] = Ah[(row + gq + 8) * LDP + ks * 8 + tq + 4];
                al[mi][0] = Al[(row + gq) * LDP + ks * 8 + tq];
                al[mi][1] = Al[(row + gq + 8) * LDP + ks * 8 + tq];
                al[mi][2] = Al[(row + gq) * LDP + ks * 8 + tq + 4];
                al[mi][3] = Al[(row + gq + 8) * LDP + ks * 8 + tq + 4];
            }
#pragma unroll
            for (int ni = 0; ni < NF; ++ni) {
                int col = wn * (NF * 8) + ni * 8;
                bh[ni][0] = Bh[(col + gq) * LDP + ks * 8 + tq];
                bh[ni][1] = Bh[(col + gq) * LDP + ks * 8 + tq + 4];
                bl[ni][0] = Bl[(col + gq) * LDP + ks * 8 + tq];
                bl[ni][1] = Bl[(col + gq) * LDP + ks * 8 + tq + 4];
            }
#pragma unroll
            for (int mi = 0; mi < MF; ++mi)
#pragma unroll
                for (int ni = 0; ni < NF; ++ni) {
                    mma_bf16(acc[mi][ni], ah[mi], bh[ni]);
                    mma_bf16(acc[mi][ni], ah[mi], bl[ni]);
                    mma_bf16(acc[mi][ni], al[mi], bh[ni]);
                }
        }
    }
    cpa_wait<0>();

#pragma unroll
    for (int mi = 0; mi < MF; ++mi)
#pragma unroll
        for (int ni = 0; ni < NF; ++ni) {
            int row = m0 + wm * (MF * 16) + mi * 16 + gq;
            int col = n0 + wn * (NF * 8) + ni * 8 + tq * 2;
#pragma unroll
            for (int hf = 0; hf < 2; ++hf) {
                int r = row + hf * 8;
                float v0 = acc[mi][ni][hf * 2 + 0] + bias[col];
                float v1 = acc[mi][ni][hf * 2 + 1] + bias[col + 1];
                *reinterpret_cast<float2*>(&g_Gin[(size_t)r * G4 + col]) =
                    make_float2(v0, v1);
            }
        }
    (void)C;
}

// ------------------------- vocab GEMM: pipelined tf32, grid-swapped ---------
// out[(b*24+t)*VOC+col] = Hb[r,:] . fcnWt[col,:] + fcn_b[col], r = t*128+b.
// blockIdx.x = m-tile (24), blockIdx.y = n-tile (250): consecutive CTAs share
// the same B n-column across all m -> fcn_W is read from DRAM once.
constexpr int VS = 3;
__global__ void __launch_bounds__(256)
gemm_vocab(const uint32_t* __restrict__ A, const uint32_t* __restrict__ Bw,
           const float* __restrict__ bias, float* __restrict__ C) {
    constexpr int BM = 128, BN = 128, BK = 32, LD = BK + 4;
    constexpr int WMS = 2, WNS = 4;
    constexpr int MF = 4, NF = 4, KS = 4;
    constexpr int KT = HH / BK;          // 32

    extern __shared__ uint32_t sv[];
    uint32_t* As = sv;                   // [VS][BM][LD]
    uint32_t* Bs = sv + VS * BM * LD;    // [VS][BN][LD]

    const int tid = threadIdx.x, lane = tid & 31, warp = tid >> 5;
    const int wm = warp % WMS, wn = warp / WMS;
    const int gq = lane >> 2, tq = lane & 3;
    const int m0 = blockIdx.x * BM, n0 = blockIdx.y * BN;   // SWAPPED

    auto loadT = [&](int st, int kt) {
#pragma unroll
        for (int it = 0; it < 4; ++it) {
            int i = tid + it * 256;
            int r = i >> 3, cq = (i & 7) * 4;
            cpa16(&As[(st * BM + r) * LD + cq],
                  &A[(size_t)(m0 + r) * HH + kt * BK + cq]);
        }
#pragma unroll
        for (int it = 0; it < 4; ++it) {
            int i = tid + it * 256;
            int r = i >> 3, cq = (i & 7) * 4;
            cpa16(&Bs[(st * BN + r) * LD + cq],
                  &Bw[(size_t)(n0 + r) * HH + kt * BK + cq]);
        }
    };

    float acc[MF][NF][4] = {};

    loadT(0, 0); cpa_commit();
    loadT(1, 1); cpa_commit();

    for (int kt = 0; kt < KT; ++kt) {
        cpa_wait<1>();
        __syncthreads();
        if (kt + 2 < KT) loadT((kt + 2) % VS, kt + 2);
        cpa_commit();

        const uint32_t* Ast = &As[(kt % VS) * BM * LD];
        const uint32_t* Bst = &Bs[(kt % VS) * BN * LD];
#pragma unroll
        for (int ks = 0; ks < KS; ++ks) {
            uint32_t af[MF][4], bf[NF][2];
#pragma unroll
            for (int mi = 0; mi < MF; ++mi) {
                int row = wm * (MF * 16) + mi * 16;
                af[mi][0] = Ast[(row + gq) * LD + ks * 8 + tq];
                af[mi][1] = Ast[(row + gq + 8) * LD + ks * 8 + tq];
                af[mi][2] = Ast[(row + gq) * LD + ks * 8 + tq + 4];
                af[mi][3] = Ast[(row + gq + 8) * LD + ks * 8 + tq + 4];
            }
#pragma unroll
            for (int ni = 0; ni < NF; ++ni) {
                int col = wn * (NF * 8) + ni * 8;
                bf[ni][0] = Bst[(col + gq) * LD + ks * 8 + tq];
                bf[ni][1] = Bst[(col + gq) * LD + ks * 8 + tq + 4];
            }
#pragma unroll
            for (int mi = 0; mi < MF; ++mi)
#pragma unroll
                for (int ni = 0; ni < NF; ++ni)
                    mma_tf32(acc[mi][ni], af[mi], bf[ni]);
        }
    }
    cpa_wait<0>();

#pragma unroll
    for (int mi = 0; mi < MF; ++mi)
#pragma unroll
        for (int ni = 0; ni < NF; ++ni) {
            int row = m0 + wm * (MF * 16) + mi * 16 + gq;
            int col = n0 + wn * (NF * 8) + ni * 8 + tq * 2;
#pragma unroll
            for (int hf = 0; hf < 2; ++hf) {
                int r = row + hf * 8;
                float v0 = acc[mi][ni][hf * 2 + 0] + bias[col];
                float v1 = acc[mi][ni][hf * 2 + 1] + bias[col + 1];
                int b = r & (BB - 1);
                int t = r >> 7;
                size_t o = ((size_t)b * (TT - 1) + t) * VOC + col;
                *reinterpret_cast<float2*>(&C[o]) = make_float2(v0, v1);
            }
        }
}

// ------------------------- recurrence step (bf16 split, fused cell) ---------
// gates = h @ W_hh^T (3-term bf16 split, all operands pre-split bf16x2) +
// Gin[t]; fused LSTM cell; emits h pre-split (bf16 hi/lo) + Hb (tf32 bits).
__global__ void __launch_bounds__(256)
rec_step(const uint32_t* __restrict__ hHi, const uint32_t* __restrict__ hLo,
         const uint32_t* __restrict__ WHi, const uint32_t* __restrict__ WLo,
         const float* __restrict__ GinT, float* __restrict__ c,
         uint32_t* __restrict__ hHiO, uint32_t* __restrict__ hLoO,
         uint32_t* __restrict__ Hb, int t) {
    constexpr int BM = 128, BN = 32, LDP = 20;
    constexpr int WMS = 4, WNS = 2;
    constexpr int MF = 2, NF = 2, KS = 2;
    constexpr int KT = HH / 32;      // 32 k-tiles of 32 (16 pairs)
    constexpr int ASW = BM * LDP;    // 2560
    constexpr int BSW = BN * LDP;    // 640

    extern __shared__ uint32_t sr[];
    uint32_t* AHs = sr;                     // [2][ASW]
    uint32_t* ALs = sr + 2 * ASW;
    uint32_t* BHs = sr + 4 * ASW;           // [2][BSW]
    uint32_t* BLs = sr + 4 * ASW + 2 * BSW;
    __shared__ float Gt[BM][BN + 1];

    const int tid = threadIdx.x, lane = tid & 31, warp = tid >> 5;
    const int wm = warp % WMS, wn = warp / WMS;
    const int gq = lane >> 2, tq = lane & 3;
    const int n0 = blockIdx.x * BN;

    float acc[MF][NF][4] = {};

    if (t > 0) {
        auto loadT = [&](int st, int kt) {
#pragma unroll
            for (int it = 0; it < 2; ++it) {      // A: 512 chunk-ids
                int i = tid + it * 256;
                int r = i >> 2, cq = (i & 3) * 4;
                cpa16(&AHs[st * ASW + r * LDP + cq],
                      &hHi[(size_t)r * HHP + kt * 16 + cq]);
                cpa16(&ALs[st * ASW + r * LDP + cq],
                      &hLo[(size_t)r * HHP + kt * 16 + cq]);
            }
            if (tid < 128) {                      // B: 128 chunk-ids
                int r = tid >> 2, cq = (tid & 3) * 4;
                cpa16(&BHs[st * BSW + r * LDP + cq],
                      &WHi[(size_t)(n0 + r) * HHP + kt * 16 + cq]);
                cpa16(&BLs[st * BSW + r * LDP + cq],
                      &WLo[(size_t)(n0 + r) * HHP + kt * 16 + cq]);
            }
        };

        loadT(0, 0); cpa_commit();

        for (int kt = 0; kt < KT; ++kt) {
            cpa_wait<0>();
            __syncthreads();
            if (kt + 1 < KT) loadT((kt + 1) & 1, kt + 1);
            cpa_commit();

            const uint32_t* Ah = &AHs[(kt & 1) * ASW];
            const uint32_t* Al = &ALs[(kt & 1) * ASW];
            const uint32_t* Bh = &BHs[(kt & 1) * BSW];
            const uint32_t* Bl = &BLs[(kt & 1) * BSW];
#pragma unroll
            for (int ks = 0; ks < KS; ++ks) {
                uint32_t ah[MF][4], al[MF][4], bh[NF][2], bl[NF][2];
#pragma unroll
                for (int mi = 0; mi < MF; ++mi) {
                    int row = wm * (MF * 16) + mi * 16;
                    ah[mi][0] = Ah[(row + gq) * LDP + ks * 8 + tq];
                    ah[mi][1] = Ah[(row + gq + 8) * LDP + ks * 8 + tq];
                    ah[mi][2] = Ah[(row + gq) * LDP + ks * 8 + tq + 4];
                    ah[mi][3] = Ah[(row + gq + 8) * LDP + ks * 8 + tq + 4];
                    al[mi][0] = Al[(row + gq) * LDP + ks * 8 + tq];
                    al[mi][1] = Al[(row + gq + 8) * LDP + ks * 8 + tq];
                    al[mi][2] = Al[(row + gq) * LDP + ks * 8 + tq + 4];
                    al[mi][3] = Al[(row + gq + 8) * LDP + ks * 8 + tq + 4];
                }
#pragma unroll
                for (int ni = 0; ni < NF; ++ni) {
                    int col = wn * (NF * 8) + ni * 8;
                    bh[ni][0] = Bh[(col + gq) * LDP + ks * 8 + tq];
                    bh[ni][1] = Bh[(col + gq) * LDP + ks * 8 + tq + 4];
                    bl[ni][0] = Bl[(col + gq) * LDP + ks * 8 + tq];
                    bl[ni][1] = Bl[(col + gq) * LDP + ks * 8 + tq + 4];
                }
#pragma unroll
                for (int mi = 0; mi < MF; ++mi)
#pragma unroll
                    for (int ni = 0; ni < NF; ++ni) {
                        mma_bf16(acc[mi][ni], ah[mi], bh[ni]);
                        mma_bf16(acc[mi][ni], ah[mi], bl[ni]);
                        mma_bf16(acc[mi][ni], al[mi], bh[ni]);
                    }
            }
        }
        cpa_wait<0>();
    }

    // ---- epilogue: stage gates (+Gin) to SMEM, then fused LSTM cell ----
#pragma unroll
    for (int mi = 0; mi < MF; ++mi)
#pragma unroll
        for (int ni = 0; ni < NF; ++ni)
#pragma unroll
            for (int hf = 0; hf < 2; ++hf) {
                int row = wm * (MF * 16) + mi * 16 + gq + hf * 8;
                int col = wn * (NF * 8) + ni * 8 + tq * 2;
                float2 ad = *reinterpret_cast<const float2*>(
                    &GinT[(size_t)row * G4 + n0 + col]);
                Gt[row][col]     = acc[mi][ni][hf * 2 + 0] + ad.x;
                Gt[row][col + 1] = acc[mi][ni][hf * 2 + 1] + ad.y;
            }
    __syncthreads();

    if (tid < BM) {
        int row = tid;
        int jbase = n0 >> 2;
        __nv_bfloat16* hHiB = reinterpret_cast<__nv_bfloat16*>(hHiO);
        __nv_bfloat16* hLoB = reinterpret_cast<__nv_bfloat16*>(hLoO);
#pragma unroll
        for (int u = 0; u < 8; ++u) {
            float gi = Gt[row][u * 4 + 0];
            float gf = Gt[row][u * 4 + 1];
            float gg = Gt[row][u * 4 + 2];
            float go = Gt[row][u * 4 + 3];
            int ci = row * HH + jbase + u;
            float cn = sigm(gf) * c[ci] + sigm(gi) * tanhf(gg);
            float hn = sigm(go) * tanhf(cn);
            c[ci] = cn;
            __nv_bfloat16 hb = __float2bfloat16_rn(hn);
            hHiB[ci] = hb;
            hLoB[ci] = __float2bfloat16_rn(hn - __bfloat162float(hb));
            if (t > 0) Hb[(size_t)(t - 1) * BB * HH + ci] = f2tf(hn);
        }
    }
}

// ------------------------- prep kernels -------------------------------------
// permutation: output row p = 4*j + gate  <-  input row = gate*HH + j
__global__ void prep_bias_k(const float* __restrict__ bi,
                            const float* __restrict__ bh, float* out) {
    int p = blockIdx.x * blockDim.x + threadIdx.x;
    if (p >= G4) return;
    int src = (p & 3) * HH + (p >> 2);
    out[p] = bi[src] + bh[src];
}

__device__ __forceinline__ void split_pair(float v0, float v1,
                                           uint32_t& hi, uint32_t& lo) {
    __nv_bfloat16 h0 = __float2bfloat16_rn(v0);
    __nv_bfloat16 h1 = __float2bfloat16_rn(v1);
    hi = pack_bf(v0, v1);  // rn-packed hi pair
    lo = pack_bf(v0 - __bfloat162float(h0), v1 - __bfloat162float(h1));
}

__global__ void prep_Wih_k(const float* __restrict__ W,
                           uint32_t* __restrict__ hi, uint32_t* __restrict__ lo) {
    int i = blockIdx.x * blockDim.x + threadIdx.x;
    if (i >= G4 * KINP) return;
    int p = i / KINP, kp = i % KINP;
    int src = (p & 3) * HH + (p >> 2);
    int k0 = 2 * kp, k1 = 2 * kp + 1;
    float v0 = (k0 < KRAW) ? W[(size_t)src * KRAW + k0] : 0.f;
    float v1 = (k1 < KRAW) ? W[(size_t)src * KRAW + k1] : 0.f;
    split_pair(v0, v1, hi[i], lo[i]);
}

__global__ void prep_Whh_k(const float* __restrict__ W,
                           uint32_t* __restrict__ hi, uint32_t* __restrict__ lo) {
    int i = blockIdx.x * blockDim.x + threadIdx.x;
    if (i >= G4 * HHP) return;
    int p = i / HHP, kp = i % HHP;
    int src = (p & 3) * HH + (p >> 2);
    float v0 = W[(size_t)src * HH + 2 * kp];
    float v1 = W[(size_t)src * HH + 2 * kp + 1];
    split_pair(v0, v1, hi[i], lo[i]);
}

__global__ void prep_fcnW_k(const float* __restrict__ W,
                            uint32_t* __restrict__ Wt) {
    size_t i = (size_t)blockIdx.x * blockDim.x + threadIdx.x;  // quad index
    if (i * 4 >= (size_t)VOC * HH) return;
    float4 v = *reinterpret_cast<const float4*>(&W[i * 4]);
    uint4 o;
    o.x = f2tf(v.x); o.y = f2tf(v.y); o.z = f2tf(v.z); o.w = f2tf(v.w);
    *reinterpret_cast<uint4*>(&Wt[i * 4]) = o;
}

__device__ __forceinline__ float xval(const float* feat, const int* caps,
                                      const float* emb, int t, int b, int k) {
    if (k < EE) {
        int tok = (t == 0) ? 1 : caps[b * TT + (t - 1)];
        return emb[(size_t)tok * EE + k];
    }
    if (k < KRAW) return feat[b * ENC + (k - EE)];
    return 0.f;
}

__global__ void prep_X_k(const float* __restrict__ feat,
                         const int* __restrict__ caps,
                         const float* __restrict__ emb,
                         uint32_t* __restrict__ hi, uint32_t* __restrict__ lo) {
    int i = blockIdx.x * blockDim.x + threadIdx.x;
    if (i >= MX * KINP) return;
    int r = i / KINP, kp = i % KINP;
    int t = r / BB, b = r % BB;
    float v0 = xval(feat, caps, emb, t, b, 2 * kp);
    float v1 = xval(feat, caps, emb, t, b, 2 * kp + 1);
    split_pair(v0, v1, hi[i], lo[i]);
}

__global__ void zero_init_k(uint32_t* hi, uint32_t* lo, float* c) {
    int i = blockIdx.x * blockDim.x + threadIdx.x;
    if (i < BB * HHP) { hi[i] = 0u; lo[i] = 0u; }
    if (i < BB * HH) c[i] = 0.f;
}

// ------------------------- launch -------------------------------------------
extern "C" void kernel_launch(void* const* d_in, const int* in_sizes, int n_in,
                              void* d_out, int out_size) {
    const float* features = (const float*)d_in[0];
    const int*   captions = (const int*)d_in[1];
    const float* emb_W    = (const float*)d_in[2];
    const float* W_ih     = (const float*)d_in[3];
    const float* W_hh     = (const float*)d_in[4];
    const float* b_ih     = (const float*)d_in[5];
    const float* b_hh     = (const float*)d_in[6];
    // d_in[7..12]: attention weights — dead (softmax over a single element)
    const float* fcn_W    = (const float*)d_in[13];
    const float* fcn_b    = (const float*)d_in[14];
    float* out = (float*)d_out;

    float *bias, *Gin, *c;
    uint32_t *Xhi, *Xlo, *WihHi, *WihLo, *WhhHi, *WhhLo, *fcnWt;
    uint32_t *hHiA, *hHiB, *hLoA, *hLoB, *Hb;
    cudaGetSymbolAddress((void**)&Xhi, g_Xhi);
    cudaGetSymbolAddress((void**)&Xlo, g_Xlo);
    cudaGetSymbolAddress((void**)&WihHi, g_WihHi);
    cudaGetSymbolAddress((void**)&WihLo, g_WihLo);
    cudaGetSymbolAddress((void**)&bias, g_bias);
    cudaGetSymbolAddress((void**)&Gin, g_Gin);
    cudaGetSymbolAddress((void**)&WhhHi, g_WhhHi);
    cudaGetSymbolAddress((void**)&WhhLo, g_WhhLo);
    cudaGetSymbolAddress((void**)&fcnWt, g_fcnWt);
    cudaGetSymbolAddress((void**)&hHiA, g_hHiA);
    cudaGetSymbolAddress((void**)&hHiB, g_hHiB);
    cudaGetSymbolAddress((void**)&hLoA, g_hLoA);
    cudaGetSymbolAddress((void**)&hLoB, g_hLoB);
    cudaGetSymbolAddress((void**)&c, g_c);
    cudaGetSymbolAddress((void**)&Hb, g_Hb);

    constexpr int SM_IN  = (4 * 128 * 20 + 4 * 128 * 20) * 4;       // 81920
    constexpr int SM_VOC = VS * (128 + 128) * 36 * 4;               // 110592
    constexpr int SM_REC = (4 * 128 * 20 + 4 * 32 * 20) * 4;        // 51200
    cudaFuncSetAttribute(gemm_in,
                         cudaFuncAttributeMaxDynamicSharedMemorySize, SM_IN);
    cudaFuncSetAttribute(gemm_vocab,
                         cudaFuncAttributeMaxDynamicSharedMemorySize, SM_VOC);
    cudaFuncSetAttribute(rec_step,
                         cudaFuncAttributeMaxDynamicSharedMemorySize, SM_REC);

    // prep
    prep_bias_k<<<(G4 + 255) / 256, 256>>>(b_ih, b_hh, bias);
    prep_Wih_k<<<(G4 * KINP + 255) / 256, 256>>>(W_ih, WihHi, WihLo);
    prep_Whh_k<<<(G4 * HHP + 255) / 256, 256>>>(W_hh, WhhHi, WhhLo);
    prep_fcnW_k<<<(VOC * HH / 4 + 255) / 256, 256>>>(fcn_W, fcnWt);
    prep_X_k<<<(MX * KINP + 255) / 256, 256>>>(features, captions, emb_W,
                                               Xhi, Xlo);
    zero_init_k<<<(BB * HH + 255) / 256, 256>>>(hHiA, hLoA, c);

    // input projection for all timesteps (permuted gate layout, bf16 split)
    gemm_in<<<dim3(G4 / 128, MX / 128), 256, SM_IN>>>(Xhi, Xlo, WihHi, WihLo,
                                                      bias, nullptr);

    // sequential LSTM, cell fused; h kept pre-split bf16, double-buffered
    uint32_t *hiP = hHiA, *loP = hLoA, *hiC = hHiB, *loC = hLoB;
    for (int t = 0; t < TT; t++) {
        rec_step<<<G4 / 32, 256, SM_REC>>>(hiP, loP, WhhHi, WhhLo,
                                           Gin + (size_t)t * BB * G4, c,
                                           hiC, loC, Hb, t);
        uint32_t* tm;
        tm = hiP; hiP = hiC; hiC = tm;
        tm = loP; loP = loC; loC = tm;
    }

    // batched vocab projection (plain tf32, cvt-free, m-fastest grid)
    gemm_vocab<<<dim3(MO / 128, VOC / 128), 256, SM_VOC>>>(Hb, fcnWt, fcn_b,
                                                           out);
}

// round 9
// speedup vs baseline: 2.4927x; 1.2477x over previous
#include <cuda_runtime.h>
#include <cuda_bf16.h>
#include <cuda_fp16.h>
#include <cstdint>

// ---------------------------------------------------------------------------
// DecoderRNNWithAttention — GB300 sm_103a, round 7
//  * attention provably dead (softmax over 1 element) -> context == features
//  * input projection + recurrence: bf16 3-term split mma.sync (R5-proven)
//  * vocab projection: plain fp16 m16n8k16 (1 instr / K=16 — half the HMMA
//    instruction count of the tf32 path), cvt-free 3-stage cp.async pipeline,
//    m-fastest grid for fcn_W L2 reuse. tcgen05 is unusable: harness compiles
//    via compute_103 virtual PTX which rejects tcgen05.
// ---------------------------------------------------------------------------

constexpr int BB  = 128;
constexpr int TT  = 25;
constexpr int EE  = 512;
constexpr int HH  = 1024;
constexpr int ENC = 400;
constexpr int VOC = 32000;
constexpr int KRAW = EE + ENC;      // 912
constexpr int KIN  = 928;           // padded to /32
constexpr int KINP = KIN / 2;       // 464 pairs
constexpr int HHP  = HH / 2;        // 512 pairs
constexpr int G4   = 4 * HH;        // 4096
constexpr int MX   = TT * BB;       // 3200
constexpr int MO   = (TT - 1) * BB; // 3072

// ------------------------- scratch (static, no cudaMalloc) -----------------
__device__ uint32_t g_Xhi[MX * KINP];            // bf16x2 pairs
__device__ uint32_t g_Xlo[MX * KINP];
__device__ uint32_t g_WihHi[G4 * KINP];
__device__ uint32_t g_WihLo[G4 * KINP];
__device__ float    g_bias[G4];
__device__ float    g_Gin[(size_t)MX * G4];
__device__ uint32_t g_WhhHi[G4 * HHP];
__device__ uint32_t g_WhhLo[G4 * HHP];
__device__ uint32_t g_fWp[(size_t)VOC * HHP];    // fcn_W as fp16x2 pairs
__device__ uint32_t g_hHiA[BB * HHP], g_hHiB[BB * HHP];   // h as bf16x2
__device__ uint32_t g_hLoA[BB * HHP], g_hLoB[BB * HHP];
__device__ float    g_c[BB * HH];
__device__ uint32_t g_Hb[(size_t)MO * HHP];      // hidden states as fp16x2

// ------------------------- helpers -----------------------------------------
__device__ __forceinline__ uint32_t pack_bf(float a, float b) {
    __nv_bfloat162 t = __floats2bfloat162_rn(a, b);
    return *reinterpret_cast<uint32_t*>(&t);
}

__device__ __forceinline__ void mma_bf16(float (&d)[4], const uint32_t (&a)[4],
                                         const uint32_t (&b)[2]) {
    asm volatile(
        "mma.sync.aligned.m16n8k16.row.col.f32.bf16.bf16.f32 "
        "{%0,%1,%2,%3},{%4,%5,%6,%7},{%8,%9},{%0,%1,%2,%3};"
        : "+f"(d[0]), "+f"(d[1]), "+f"(d[2]), "+f"(d[3])
        : "r"(a[0]), "r"(a[1]), "r"(a[2]), "r"(a[3]), "r"(b[0]), "r"(b[1]));
}

__device__ __forceinline__ void mma_fp16(float (&d)[4], const uint32_t (&a)[4],
                                         const uint32_t (&b)[2]) {
    asm volatile(
        "mma.sync.aligned.m16n8k16.row.col.f32.f16.f16.f32 "
        "{%0,%1,%2,%3},{%4,%5,%6,%7},{%8,%9},{%0,%1,%2,%3};"
        : "+f"(d[0]), "+f"(d[1]), "+f"(d[2]), "+f"(d[3])
        : "r"(a[0]), "r"(a[1]), "r"(a[2]), "r"(a[3]), "r"(b[0]), "r"(b[1]));
}

__device__ __forceinline__ void cpa16p(void* s, const void* g) {
    uint32_t sa = (uint32_t)__cvta_generic_to_shared(s);
    asm volatile("cp.async.cg.shared.global [%0], [%1], 16;" ::"r"(sa), "l"(g));
}
__device__ __forceinline__ void cpa_commit() {
    asm volatile("cp.async.commit_group;");
}
template <int N> __device__ __forceinline__ void cpa_wait() {
    asm volatile("cp.async.wait_group %0;" ::"n"(N));
}

__device__ __forceinline__ float sigm(float x) { return 1.f / (1.f + expf(-x)); }

// ------------------------- input GEMM (R5-proven) ---------------------------
__global__ void __launch_bounds__(256)
gemm_in(const uint32_t* __restrict__ Ahi, const uint32_t* __restrict__ Alo,
        const uint32_t* __restrict__ Bhi, const uint32_t* __restrict__ Blo,
        const float* __restrict__ bias) {
    constexpr int BM = 128, BN = 128, LDP = 20;
    constexpr int WMS = 2, WNS = 4;
    constexpr int MF = 4, NF = 4, KS = 2;
    constexpr int KT = KIN / 32;                    // 29
    constexpr int ASW = BM * LDP;
    constexpr int BSW = BN * LDP;

    extern __shared__ uint32_t sm[];
    uint32_t* AHs = sm;
    uint32_t* ALs = sm + 2 * ASW;
    uint32_t* BHs = sm + 4 * ASW;
    uint32_t* BLs = sm + 4 * ASW + 2 * BSW;

    const int tid = threadIdx.x, lane = tid & 31, warp = tid >> 5;
    const int wm = warp % WMS, wn = warp / WMS;
    const int gq = lane >> 2, tq = lane & 3;
    const int m0 = blockIdx.y * BM, n0 = blockIdx.x * BN;

    auto loadT = [&](int st, int kt) {
#pragma unroll
        for (int it = 0; it < 2; ++it) {
            int i = tid + it * 256;
            int r = i >> 2, cq = (i & 3) * 4;
            cpa16p(&AHs[st * ASW + r * LDP + cq],
                   &Ahi[(size_t)(m0 + r) * KINP + kt * 16 + cq]);
            cpa16p(&ALs[st * ASW + r * LDP + cq],
                   &Alo[(size_t)(m0 + r) * KINP + kt * 16 + cq]);
            cpa16p(&BHs[st * BSW + r * LDP + cq],
                   &Bhi[(size_t)(n0 + r) * KINP + kt * 16 + cq]);
            cpa16p(&BLs[st * BSW + r * LDP + cq],
                   &Blo[(size_t)(n0 + r) * KINP + kt * 16 + cq]);
        }
    };

    float acc[MF][NF][4] = {};

    loadT(0, 0); cpa_commit();

    for (int kt = 0; kt < KT; ++kt) {
        cpa_wait<0>();
        __syncthreads();
        if (kt + 1 < KT) loadT((kt + 1) & 1, kt + 1);
        cpa_commit();

        const uint32_t* Ah = &AHs[(kt & 1) * ASW];
        const uint32_t* Al = &ALs[(kt & 1) * ASW];
        const uint32_t* Bh = &BHs[(kt & 1) * BSW];
        const uint32_t* Bl = &BLs[(kt & 1) * BSW];
#pragma unroll
        for (int ks = 0; ks < KS; ++ks) {
            uint32_t ah[MF][4], al[MF][4], bh[NF][2], bl[NF][2];
#pragma unroll
            for (int mi = 0; mi < MF; ++mi) {
                int row = wm * (MF * 16) + mi * 16;
                ah[mi][0] = Ah[(row + gq) * LDP + ks * 8 + tq];
                ah[mi][1] = Ah[(row + gq + 8) * LDP + ks * 8 + tq];
                ah[mi][2] = Ah[(row + gq) * LDP + ks * 8 + tq + 4];
                ah[mi][3] = Ah[(row + gq + 8) * LDP + ks * 8 + tq + 4];
                al[mi][0] = Al[(row + gq) * LDP + ks * 8 + tq];
                al[mi][1] = Al[(row + gq + 8) * LDP + ks * 8 + tq];
                al[mi][2] = Al[(row + gq) * LDP + ks * 8 + tq + 4];
                al[mi][3] = Al[(row + gq + 8) * LDP + ks * 8 + tq + 4];
            }
#pragma unroll
            for (int ni = 0; ni < NF; ++ni) {
                int col = wn * (NF * 8) + ni * 8;
                bh[ni][0] = Bh[(col + gq) * LDP + ks * 8 + tq];
                bh[ni][1] = Bh[(col + gq) * LDP + ks * 8 + tq + 4];
                bl[ni][0] = Bl[(col + gq) * LDP + ks * 8 + tq];
                bl[ni][1] = Bl[(col + gq) * LDP + ks * 8 + tq + 4];
            }
#pragma unroll
            for (int mi = 0; mi < MF; ++mi)
#pragma unroll
                for (int ni = 0; ni < NF; ++ni) {
                    mma_bf16(acc[mi][ni], ah[mi], bh[ni]);
                    mma_bf16(acc[mi][ni], ah[mi], bl[ni]);
                    mma_bf16(acc[mi][ni], al[mi], bh[ni]);
                }
        }
    }
    cpa_wait<0>();

#pragma unroll
    for (int mi = 0; mi < MF; ++mi)
#pragma unroll
        for (int ni = 0; ni < NF; ++ni) {
            int row = m0 + wm * (MF * 16) + mi * 16 + gq;
            int col = n0 + wn * (NF * 8) + ni * 8 + tq * 2;
#pragma unroll
            for (int hf = 0; hf < 2; ++hf) {
                int r = row + hf * 8;
                float v0 = acc[mi][ni][hf * 2 + 0] + bias[col];
                float v1 = acc[mi][ni][hf * 2 + 1] + bias[col + 1];
                *reinterpret_cast<float2*>(&g_Gin[(size_t)r * G4 + col]) =
                    make_float2(v0, v1);
            }
        }
}

// ------------------------- vocab GEMM: plain fp16, pipelined ----------------
// out[(b*24+t)*VOC+col] = Hb[r,:] . fW[col,:] + fcn_b[col], r = t*128+b.
// Operands pre-converted to fp16x2; 1 mma per K=16; 3-stage cp.async.
// blockIdx.x = m-tile (24, fastest) -> each fcn_W tile DRAM-read once.
constexpr int VS = 3;
__global__ void __launch_bounds__(256)
gemm_vocab(const uint32_t* __restrict__ A, const uint32_t* __restrict__ Bw,
           const float* __restrict__ bias, float* __restrict__ C) {
    constexpr int BM = 128, BN = 128, LDP = 20;     // 16 pairs + 4 pad
    constexpr int WMS = 2, WNS = 4;
    constexpr int MF = 4, NF = 4, KS = 2;
    constexpr int KT = HH / 32;                     // 32
    constexpr int ASW = BM * LDP;                   // 2560
    constexpr int BSW = BN * LDP;

    extern __shared__ uint32_t sv[];
    uint32_t* As = sv;                   // [VS][ASW]
    uint32_t* Bs = sv + VS * ASW;        // [VS][BSW]

    const int tid = threadIdx.x, lane = tid & 31, warp = tid >> 5;
    const int wm = warp % WMS, wn = warp / WMS;
    const int gq = lane >> 2, tq = lane & 3;
    const int m0 = blockIdx.x * BM, n0 = blockIdx.y * BN;   // m fastest

    auto loadT = [&](int st, int kt) {
#pragma unroll
        for (int it = 0; it < 2; ++it) {
            int i = tid + it * 256;
            int r = i >> 2, cq = (i & 3) * 4;
            cpa16p(&As[st * ASW + r * LDP + cq],
                   &A[(size_t)(m0 + r) * HHP + kt * 16 + cq]);
            cpa16p(&Bs[st * BSW + r * LDP + cq],
                   &Bw[(size_t)(n0 + r) * HHP + kt * 16 + cq]);
        }
    };

    float acc[MF][NF][4] = {};

    loadT(0, 0); cpa_commit();
    loadT(1, 1); cpa_commit();

    for (int kt = 0; kt < KT; ++kt) {
        cpa_wait<1>();
        __syncthreads();
        if (kt + 2 < KT) loadT((kt + 2) % VS, kt + 2);
        cpa_commit();

        const uint32_t* Ast = &As[(kt % VS) * ASW];
        const uint32_t* Bst = &Bs[(kt % VS) * BSW];
#pragma unroll
        for (int ks = 0; ks < KS; ++ks) {
            uint32_t af[MF][4], bf[NF][2];
#pragma unroll
            for (int mi = 0; mi < MF; ++mi) {
                int row = wm * (MF * 16) + mi * 16;
                af[mi][0] = Ast[(row + gq) * LDP + ks * 8 + tq];
                af[mi][1] = Ast[(row + gq + 8) * LDP + ks * 8 + tq];
                af[mi][2] = Ast[(row + gq) * LDP + ks * 8 + tq + 4];
                af[mi][3] = Ast[(row + gq + 8) * LDP + ks * 8 + tq + 4];
            }
#pragma unroll
            for (int ni = 0; ni < NF; ++ni) {
                int col = wn * (NF * 8) + ni * 8;
                bf[ni][0] = Bst[(col + gq) * LDP + ks * 8 + tq];
                bf[ni][1] = Bst[(col + gq) * LDP + ks * 8 + tq + 4];
            }
#pragma unroll
            for (int mi = 0; mi < MF; ++mi)
#pragma unroll
                for (int ni = 0; ni < NF; ++ni)
                    mma_fp16(acc[mi][ni], af[mi], bf[ni]);
        }
    }
    cpa_wait<0>();

#pragma unroll
    for (int mi = 0; mi < MF; ++mi)
#pragma unroll
        for (int ni = 0; ni < NF; ++ni) {
            int row = m0 + wm * (MF * 16) + mi * 16 + gq;
            int col = n0 + wn * (NF * 8) + ni * 8 + tq * 2;
#pragma unroll
            for (int hf = 0; hf < 2; ++hf) {
                int r = row + hf * 8;
                float v0 = acc[mi][ni][hf * 2 + 0] + bias[col];
                float v1 = acc[mi][ni][hf * 2 + 1] + bias[col + 1];
                int b = r & (BB - 1);
                int t = r >> 7;
                size_t o = ((size_t)b * (TT - 1) + t) * VOC + col;
                *reinterpret_cast<float2*>(&C[o]) = make_float2(v0, v1);
            }
        }
}

// ------------------------- recurrence step (R5-proven, fp16 Hb out) ---------
__global__ void __launch_bounds__(256)
rec_step(const uint32_t* __restrict__ hHi, const uint32_t* __restrict__ hLo,
         const uint32_t* __restrict__ WHi, const uint32_t* __restrict__ WLo,
         const float* __restrict__ GinT, float* __restrict__ c,
         uint32_t* __restrict__ hHiO, uint32_t* __restrict__ hLoO,
         uint32_t* __restrict__ Hb, int t) {
    constexpr int BM = 128, BN = 32, LDP = 20;
    constexpr int WMS = 4, WNS = 2;
    constexpr int MF = 2, NF = 2, KS = 2;
    constexpr int KT = HH / 32;
    constexpr int ASW = BM * LDP;
    constexpr int BSW = BN * LDP;

    extern __shared__ uint32_t sr[];
    uint32_t* AHs = sr;
    uint32_t* ALs = sr + 2 * ASW;
    uint32_t* BHs = sr + 4 * ASW;
    uint32_t* BLs = sr + 4 * ASW + 2 * BSW;
    __shared__ float Gt[BM][BN + 1];

    const int tid = threadIdx.x, lane = tid & 31, warp = tid >> 5;
    const int wm = warp % WMS, wn = warp / WMS;
    const int gq = lane >> 2, tq = lane & 3;
    const int n0 = blockIdx.x * BN;

    float acc[MF][NF][4] = {};

    if (t > 0) {
        auto loadT = [&](int st, int kt) {
#pragma unroll
            for (int it = 0; it < 2; ++it) {
                int i = tid + it * 256;
                int r = i >> 2, cq = (i & 3) * 4;
                cpa16p(&AHs[st * ASW + r * LDP + cq],
                       &hHi[(size_t)r * HHP + kt * 16 + cq]);
                cpa16p(&ALs[st * ASW + r * LDP + cq],
                       &hLo[(size_t)r * HHP + kt * 16 + cq]);
            }
            if (tid < 128) {
                int r = tid >> 2, cq = (tid & 3) * 4;
                cpa16p(&BHs[st * BSW + r * LDP + cq],
                       &WHi[(size_t)(n0 + r) * HHP + kt * 16 + cq]);
                cpa16p(&BLs[st * BSW + r * LDP + cq],
                       &WLo[(size_t)(n0 + r) * HHP + kt * 16 + cq]);
            }
        };

        loadT(0, 0); cpa_commit();

        for (int kt = 0; kt < KT; ++kt) {
            cpa_wait<0>();
            __syncthreads();
            if (kt + 1 < KT) loadT((kt + 1) & 1, kt + 1);
            cpa_commit();

            const uint32_t* Ah = &AHs[(kt & 1) * ASW];
            const uint32_t* Al = &ALs[(kt & 1) * ASW];
            const uint32_t* Bh = &BHs[(kt & 1) * BSW];
            const uint32_t* Bl = &BLs[(kt & 1) * BSW];
#pragma unroll
            for (int ks = 0; ks < KS; ++ks) {
                uint32_t ah[MF][4], al[MF][4], bh[NF][2], bl[NF][2];
#pragma unroll
                for (int mi = 0; mi < MF; ++mi) {
                    int row = wm * (MF * 16) + mi * 16;
                    ah[mi][0] = Ah[(row + gq) * LDP + ks * 8 + tq];
                    ah[mi][1] = Ah[(row + gq + 8) * LDP + ks * 8 + tq];
                    ah[mi][2] = Ah[(row + gq) * LDP + ks * 8 + tq + 4];
                    ah[mi][3] = Ah[(row + gq + 8) * LDP + ks * 8 + tq + 4];
                    al[mi][0] = Al[(row + gq) * LDP + ks * 8 + tq];
                    al[mi][1] = Al[(row + gq + 8) * LDP + ks * 8 + tq];
                    al[mi][2] = Al[(row + gq) * LDP + ks * 8 + tq + 4];
                    al[mi][3] = Al[(row + gq + 8) * LDP + ks * 8 + tq + 4];
                }
#pragma unroll
                for (int ni = 0; ni < NF; ++ni) {
                    int col = wn * (NF * 8) + ni * 8;
                    bh[ni][0] = Bh[(col + gq) * LDP + ks * 8 + tq];
                    bh[ni][1] = Bh[(col + gq) * LDP + ks * 8 + tq + 4];
                    bl[ni][0] = Bl[(col + gq) * LDP + ks * 8 + tq];
                    bl[ni][1] = Bl[(col + gq) * LDP + ks * 8 + tq + 4];
                }
#pragma unroll
                for (int mi = 0; mi < MF; ++mi)
#pragma unroll
                    for (int ni = 0; ni < NF; ++ni) {
                        mma_bf16(acc[mi][ni], ah[mi], bh[ni]);
                        mma_bf16(acc[mi][ni], ah[mi], bl[ni]);
                        mma_bf16(acc[mi][ni], al[mi], bh[ni]);
                    }
            }
        }
        cpa_wait<0>();
    }

    // ---- epilogue: stage gates (+Gin) to SMEM, then fused LSTM cell ----
#pragma unroll
    for (int mi = 0; mi < MF; ++mi)
#pragma unroll
        for (int ni = 0; ni < NF; ++ni)
#pragma unroll
            for (int hf = 0; hf < 2; ++hf) {
                int row = wm * (MF * 16) + mi * 16 + gq + hf * 8;
                int col = wn * (NF * 8) + ni * 8 + tq * 2;
                float2 ad = *reinterpret_cast<const float2*>(
                    &GinT[(size_t)row * G4 + n0 + col]);
                Gt[row][col]     = acc[mi][ni][hf * 2 + 0] + ad.x;
                Gt[row][col + 1] = acc[mi][ni][hf * 2 + 1] + ad.y;
            }
    __syncthreads();

    if (tid < BM) {
        int row = tid;
        int jbase = n0 >> 2;
        __nv_bfloat16* hHiB = reinterpret_cast<__nv_bfloat16*>(hHiO);
        __nv_bfloat16* hLoB = reinterpret_cast<__nv_bfloat16*>(hLoO);
        __half* HbH = reinterpret_cast<__half*>(Hb);
#pragma unroll
        for (int u = 0; u < 8; ++u) {
            float gi = Gt[row][u * 4 + 0];
            float gf = Gt[row][u * 4 + 1];
            float gg = Gt[row][u * 4 + 2];
            float go = Gt[row][u * 4 + 3];
            int ci = row * HH + jbase + u;
            float cn = sigm(gf) * c[ci] + sigm(gi) * tanhf(gg);
            float hn = sigm(go) * tanhf(cn);
            c[ci] = cn;
            __nv_bfloat16 hb = __float2bfloat16_rn(hn);
            hHiB[ci] = hb;
            hLoB[ci] = __float2bfloat16_rn(hn - __bfloat162float(hb));
            if (t > 0)
                HbH[(size_t)(t - 1) * BB * HH + ci] = __float2half_rn(hn);
        }
    }
}

// ------------------------- prep kernels -------------------------------------
__global__ void prep_bias_k(const float* __restrict__ bi,
                            const float* __restrict__ bh, float* out) {
    int p = blockIdx.x * blockDim.x + threadIdx.x;
    if (p >= G4) return;
    int src = (p & 3) * HH + (p >> 2);
    out[p] = bi[src] + bh[src];
}

__device__ __forceinline__ void split_pair(float v0, float v1,
                                           uint32_t& hi, uint32_t& lo) {
    __nv_bfloat16 h0 = __float2bfloat16_rn(v0);
    __nv_bfloat16 h1 = __float2bfloat16_rn(v1);
    hi = pack_bf(v0, v1);
    lo = pack_bf(v0 - __bfloat162float(h0), v1 - __bfloat162float(h1));
}

__global__ void prep_Wih_k(const float* __restrict__ W,
                           uint32_t* __restrict__ hi, uint32_t* __restrict__ lo) {
    int i = blockIdx.x * blockDim.x + threadIdx.x;
    if (i >= G4 * KINP) return;
    int p = i / KINP, kp = i % KINP;
    int src = (p & 3) * HH + (p >> 2);
    int k0 = 2 * kp, k1 = 2 * kp + 1;
    float v0 = (k0 < KRAW) ? W[(size_t)src * KRAW + k0] : 0.f;
    float v1 = (k1 < KRAW) ? W[(size_t)src * KRAW + k1] : 0.f;
    split_pair(v0, v1, hi[i], lo[i]);
}

__global__ void prep_Whh_k(const float* __restrict__ W,
                           uint32_t* __restrict__ hi, uint32_t* __restrict__ lo) {
    int i = blockIdx.x * blockDim.x + threadIdx.x;
    if (i >= G4 * HHP) return;
    int p = i / HHP, kp = i % HHP;
    int src = (p & 3) * HH + (p >> 2);
    float v0 = W[(size_t)src * HH + 2 * kp];
    float v1 = W[(size_t)src * HH + 2 * kp + 1];
    split_pair(v0, v1, hi[i], lo[i]);
}

__global__ void prep_fcnW_k(const float* __restrict__ W,
                            uint32_t* __restrict__ Wp) {
    size_t i = (size_t)blockIdx.x * blockDim.x + threadIdx.x;  // 2-pair index
    if (i * 2 >= (size_t)VOC * HHP) return;
    float4 v = *reinterpret_cast<const float4*>(&W[i * 4]);
    __half2 p0 = __floats2half2_rn(v.x, v.y);
    __half2 p1 = __floats2half2_rn(v.z, v.w);
    *reinterpret_cast<uint2*>(&Wp[i * 2]) =
        make_uint2(*reinterpret_cast<uint32_t*>(&p0),
                   *reinterpret_cast<uint32_t*>(&p1));
}

__device__ __forceinline__ float xval(const float* feat, const int* caps,
                                      const float* emb, int t, int b, int k) {
    if (k < EE) {
        int tok = (t == 0) ? 1 : caps[b * TT + (t - 1)];
        return emb[(size_t)tok * EE + k];
    }
    if (k < KRAW) return feat[b * ENC + (k - EE)];
    return 0.f;
}

__global__ void prep_X_k(const float* __restrict__ feat,
                         const int* __restrict__ caps,
                         const float* __restrict__ emb,
                         uint32_t* __restrict__ hi, uint32_t* __restrict__ lo) {
    int i = blockIdx.x * blockDim.x + threadIdx.x;
    if (i >= MX * KINP) return;
    int r = i / KINP, kp = i % KINP;
    int t = r / BB, b = r % BB;
    float v0 = xval(feat, caps, emb, t, b, 2 * kp);
    float v1 = xval(feat, caps, emb, t, b, 2 * kp + 1);
    split_pair(v0, v1, hi[i], lo[i]);
}

__global__ void zero_init_k(uint32_t* hi, uint32_t* lo, float* c) {
    int i = blockIdx.x * blockDim.x + threadIdx.x;
    if (i < BB * HHP) { hi[i] = 0u; lo[i] = 0u; }
    if (i < BB * HH) c[i] = 0.f;
}

// ------------------------- launch -------------------------------------------
extern "C" void kernel_launch(void* const* d_in, const int* in_sizes, int n_in,
                              void* d_out, int out_size) {
    const float* features = (const float*)d_in[0];
    const int*   captions = (const int*)d_in[1];
    const float* emb_W    = (const float*)d_in[2];
    const float* W_ih     = (const float*)d_in[3];
    const float* W_hh     = (const float*)d_in[4];
    const float* b_ih     = (const float*)d_in[5];
    const float* b_hh     = (const float*)d_in[6];
    // d_in[7..12]: attention weights — dead (softmax over a single element)
    const float* fcn_W    = (const float*)d_in[13];
    const float* fcn_b    = (const float*)d_in[14];
    float* out = (float*)d_out;

    float *bias, *Gin, *c;
    uint32_t *Xhi, *Xlo, *WihHi, *WihLo, *WhhHi, *WhhLo, *fWp;
    uint32_t *hHiA, *hHiB, *hLoA, *hLoB, *Hb;
    cudaGetSymbolAddress((void**)&Xhi, g_Xhi);
    cudaGetSymbolAddress((void**)&Xlo, g_Xlo);
    cudaGetSymbolAddress((void**)&WihHi, g_WihHi);
    cudaGetSymbolAddress((void**)&WihLo, g_WihLo);
    cudaGetSymbolAddress((void**)&bias, g_bias);
    cudaGetSymbolAddress((void**)&Gin, g_Gin);
    cudaGetSymbolAddress((void**)&WhhHi, g_WhhHi);
    cudaGetSymbolAddress((void**)&WhhLo, g_WhhLo);
    cudaGetSymbolAddress((void**)&fWp, g_fWp);
    cudaGetSymbolAddress((void**)&hHiA, g_hHiA);
    cudaGetSymbolAddress((void**)&hHiB, g_hHiB);
    cudaGetSymbolAddress((void**)&hLoA, g_hLoA);
    cudaGetSymbolAddress((void**)&hLoB, g_hLoB);
    cudaGetSymbolAddress((void**)&c, g_c);
    cudaGetSymbolAddress((void**)&Hb, g_Hb);

    constexpr int SM_IN  = (4 * 128 * 20 + 4 * 128 * 20) * 4;   // 81920
    constexpr int SM_VOC = VS * (128 * 20 + 128 * 20) * 4;      // 61440
    constexpr int SM_REC = (4 * 128 * 20 + 4 * 32 * 20) * 4;    // 51200
    cudaFuncSetAttribute(gemm_in,
                         cudaFuncAttributeMaxDynamicSharedMemorySize, SM_IN);
    cudaFuncSetAttribute(gemm_vocab,
                         cudaFuncAttributeMaxDynamicSharedMemorySize, SM_VOC);
    cudaFuncSetAttribute(rec_step,
                         cudaFuncAttributeMaxDynamicSharedMemorySize, SM_REC);

    // prep
    prep_bias_k<<<(G4 + 255) / 256, 256>>>(b_ih, b_hh, bias);
    prep_Wih_k<<<(G4 * KINP + 255) / 256, 256>>>(W_ih, WihHi, WihLo);
    prep_Whh_k<<<(G4 * HHP + 255) / 256, 256>>>(W_hh, WhhHi, WhhLo);
    prep_fcnW_k<<<((int)((size_t)VOC * HHP / 2) + 255) / 256, 256>>>(fcn_W, fWp);
    prep_X_k<<<(MX * KINP + 255) / 256, 256>>>(features, captions, emb_W,
                                               Xhi, Xlo);
    zero_init_k<<<(BB * HH + 255) / 256, 256>>>(hHiA, hLoA, c);

    // input projection for all timesteps (permuted gate layout, bf16 split)
    gemm_in<<<dim3(G4 / 128, MX / 128), 256, SM_IN>>>(Xhi, Xlo, WihHi, WihLo,
                                                      bias);

    // sequential LSTM, cell fused; h kept pre-split bf16, double-buffered
    uint32_t *hiP = hHiA, *loP = hLoA, *hiC = hHiB, *loC = hLoB;
    for (int t = 0; t < TT; t++) {
        rec_step<<<G4 / 32, 256, SM_REC>>>(hiP, loP, WhhHi, WhhLo,
                                           Gin + (size_t)t * BB * G4, c,
                                           hiC, loC, Hb, t);
        uint32_t* tm;
        tm = hiP; hiP = hiC; hiC = tm;
        tm = loP; loP = loC; loC = tm;
    }

    // batched vocab projection (plain fp16, cvt-free, m-fastest grid)
    gemm_vocab<<<dim3(MO / 128, VOC / 128), 256, SM_VOC>>>(Hb, fWp, fcn_b,
                                                           out);
}

// round 10
// speedup vs baseline: 2.9913x; 1.2000x over previous
#include <cuda_runtime.h>
#include <cuda_bf16.h>
#include <cuda_fp16.h>
#include <cstdint>

// ---------------------------------------------------------------------------
// DecoderRNNWithAttention — GB300 sm_103a, round 9
//  * attention provably dead (softmax over 1 element) -> context == features
//  * ldmatrix.x4 fragment loads in all mma kernels (4x fewer load instrs)
//  * recurrence: ONE persistent kernel, W_hh resident in SMEM, c in
//    registers, spin grid-barrier between steps (128 CTAs, all resident)
//  * vocab projection: plain fp16 m16n8k16, 3-stage cp.async, m-fastest grid
// ---------------------------------------------------------------------------

constexpr int BB  = 128;
constexpr int TT  = 25;
constexpr int EE  = 512;
constexpr int HH  = 1024;
constexpr int ENC = 400;
constexpr int VOC = 32000;
constexpr int KRAW = EE + ENC;      // 912
constexpr int KIN  = 928;           // padded to /32
constexpr int KINP = KIN / 2;       // 464 pairs
constexpr int HHP  = HH / 2;        // 512 pairs
constexpr int G4   = 4 * HH;        // 4096
constexpr int MX   = TT * BB;       // 3200
constexpr int MO   = (TT - 1) * BB; // 3072

// ------------------------- scratch (static, no cudaMalloc) -----------------
__device__ uint32_t g_Xhi[MX * KINP];            // bf16x2 pairs
__device__ uint32_t g_Xlo[MX * KINP];
__device__ uint32_t g_WihHi[G4 * KINP];
__device__ uint32_t g_WihLo[G4 * KINP];
__device__ float    g_bias[G4];
__device__ float    g_Gin[(size_t)MX * G4];
__device__ uint32_t g_WhhHi[G4 * HHP];
__device__ uint32_t g_WhhLo[G4 * HHP];
__device__ uint32_t g_fWp[(size_t)VOC * HHP];    // fcn_W as fp16x2 pairs
__device__ uint32_t g_hHiA[BB * HHP], g_hHiB[BB * HHP];   // h as bf16x2
__device__ uint32_t g_hLoA[BB * HHP], g_hLoB[BB * HHP];
__device__ uint32_t g_Hb[(size_t)MO * HHP];      // hidden states as fp16x2
__device__ unsigned g_barctr;                    // grid barrier counter

// ------------------------- helpers -----------------------------------------
__device__ __forceinline__ uint32_t pack_bf(float a, float b) {
    __nv_bfloat162 t = __floats2bfloat162_rn(a, b);
    return *reinterpret_cast<uint32_t*>(&t);
}

__device__ __forceinline__ void mma_bf16(float (&d)[4], const uint32_t (&a)[4],
                                         uint32_t b0, uint32_t b1) {
    asm volatile(
        "mma.sync.aligned.m16n8k16.row.col.f32.bf16.bf16.f32 "
        "{%0,%1,%2,%3},{%4,%5,%6,%7},{%8,%9},{%0,%1,%2,%3};"
        : "+f"(d[0]), "+f"(d[1]), "+f"(d[2]), "+f"(d[3])
        : "r"(a[0]), "r"(a[1]), "r"(a[2]), "r"(a[3]), "r"(b0), "r"(b1));
}

__device__ __forceinline__ void mma_fp16(float (&d)[4], const uint32_t (&a)[4],
                                         uint32_t b0, uint32_t b1) {
    asm volatile(
        "mma.sync.aligned.m16n8k16.row.col.f32.f16.f16.f32 "
        "{%0,%1,%2,%3},{%4,%5,%6,%7},{%8,%9},{%0,%1,%2,%3};"
        : "+f"(d[0]), "+f"(d[1]), "+f"(d[2]), "+f"(d[3])
        : "r"(a[0]), "r"(a[1]), "r"(a[2]), "r"(a[3]), "r"(b0), "r"(b1));
}

__device__ __forceinline__ void ldsm_x4(uint32_t (&r)[4], uint32_t addr) {
    asm volatile(
        "ldmatrix.sync.aligned.m8n8.x4.shared.b16 {%0,%1,%2,%3}, [%4];"
        : "=r"(r[0]), "=r"(r[1]), "=r"(r[2]), "=r"(r[3]) : "r"(addr));
}

__device__ __forceinline__ void cpa16p(void* s, const void* g) {
    uint32_t sa = (uint32_t)__cvta_generic_to_shared(s);
    asm volatile("cp.async.cg.shared.global [%0], [%1], 16;" ::"r"(sa), "l"(g));
}
__device__ __forceinline__ void cpa_commit() {
    asm volatile("cp.async.commit_group;");
}
template <int N> __device__ __forceinline__ void cpa_wait() {
    asm volatile("cp.async.wait_group %0;" ::"n"(N));
}

__device__ __forceinline__ float sigm(float x) { return 1.f / (1.f + expf(-x)); }

// all-threads fence, then thread0 arrives + spins; safe: 128 CTAs all resident
__device__ __forceinline__ void grid_bar(unsigned target) {
    __threadfence();
    __syncthreads();
    if (threadIdx.x == 0) {
        atomicAdd(&g_barctr, 1u);
        volatile unsigned* p = &g_barctr;
        while (*p < target) {}
    }
    __syncthreads();
    __threadfence();
}

// ------------------------- input GEMM (bf16 3-term split, ldmatrix) ---------
__global__ void __launch_bounds__(256)
gemm_in(const uint32_t* __restrict__ Ahi, const uint32_t* __restrict__ Alo,
        const uint32_t* __restrict__ Bhi, const uint32_t* __restrict__ Blo,
        const float* __restrict__ bias) {
    constexpr int BM = 128, BN = 128, LDP = 20;
    constexpr int WMS = 2, WNS = 4;
    constexpr int MF = 4, NF = 4, KS = 2;
    constexpr int KT = KIN / 32;                    // 29
    constexpr int ASW = BM * LDP;
    constexpr int BSW = BN * LDP;

    extern __shared__ uint32_t sm[];
    uint32_t* AHs = sm;
    uint32_t* ALs = sm + 2 * ASW;
    uint32_t* BHs = sm + 4 * ASW;
    uint32_t* BLs = sm + 4 * ASW + 2 * BSW;

    const int tid = threadIdx.x, lane = tid & 31, warp = tid >> 5;
    const int wm = warp % WMS, wn = warp / WMS;
    const int gq = lane >> 2, tq = lane & 3;
    const int m0 = blockIdx.y * BM, n0 = blockIdx.x * BN;

    const int mmid = lane >> 3, rr = lane & 7;
    const int arow = (mmid & 1) * 8 + rr, acolw = (mmid >> 1) * 4;
    const int brow = (mmid >> 1) * 8 + rr, bcolw = (mmid & 1) * 4;
    const uint32_t AHu = (uint32_t)__cvta_generic_to_shared(AHs);
    const uint32_t ALu = (uint32_t)__cvta_generic_to_shared(ALs);
    const uint32_t BHu = (uint32_t)__cvta_generic_to_shared(BHs);
    const uint32_t BLu = (uint32_t)__cvta_generic_to_shared(BLs);

    auto loadT = [&](int st, int kt) {
#pragma unroll
        for (int it = 0; it < 2; ++it) {
            int i = tid + it * 256;
            int r = i >> 2, cq = (i & 3) * 4;
            cpa16p(&AHs[st * ASW + r * LDP + cq],
                   &Ahi[(size_t)(m0 + r) * KINP + kt * 16 + cq]);
            cpa16p(&ALs[st * ASW + r * LDP + cq],
                   &Alo[(size_t)(m0 + r) * KINP + kt * 16 + cq]);
            cpa16p(&BHs[st * BSW + r * LDP + cq],
                   &Bhi[(size_t)(n0 + r) * KINP + kt * 16 + cq]);
            cpa16p(&BLs[st * BSW + r * LDP + cq],
                   &Blo[(size_t)(n0 + r) * KINP + kt * 16 + cq]);
        }
    };

    float acc[MF][NF][4] = {};

    loadT(0, 0); cpa_commit();

    for (int kt = 0; kt < KT; ++kt) {
        cpa_wait<0>();
        __syncthreads();
        if (kt + 1 < KT) loadT((kt + 1) & 1, kt + 1);
        cpa_commit();

        const uint32_t so = (kt & 1) * ASW * 4;
        const uint32_t sob = (kt & 1) * BSW * 4;
#pragma unroll
        for (int ks = 0; ks < KS; ++ks) {
            uint32_t ah[MF][4], al[MF][4], bh[2][4], bl[2][4];
#pragma unroll
            for (int mi = 0; mi < MF; ++mi) {
                uint32_t off = ((wm * 64 + mi * 16 + arow) * LDP +
                                ks * 8 + acolw) * 4;
                ldsm_x4(ah[mi], AHu + so + off);
                ldsm_x4(al[mi], ALu + so + off);
            }
#pragma unroll
            for (int nb = 0; nb < 2; ++nb) {
                uint32_t off = ((wn * 32 + nb * 16 + brow) * LDP +
                                ks * 8 + bcolw) * 4;
                ldsm_x4(bh[nb], BHu + sob + off);
                ldsm_x4(bl[nb], BLu + sob + off);
            }
#pragma unroll
            for (int mi = 0; mi < MF; ++mi)
#pragma unroll
                for (int ni = 0; ni < NF; ++ni) {
                    uint32_t h0 = bh[ni >> 1][(ni & 1) * 2];
                    uint32_t h1 = bh[ni >> 1][(ni & 1) * 2 + 1];
                    uint32_t l0 = bl[ni >> 1][(ni & 1) * 2];
                    uint32_t l1 = bl[ni >> 1][(ni & 1) * 2 + 1];
                    mma_bf16(acc[mi][ni], ah[mi], h0, h1);
                    mma_bf16(acc[mi][ni], ah[mi], l0, l1);
                    mma_bf16(acc[mi][ni], al[mi], h0, h1);
                }
        }
    }
    cpa_wait<0>();

#pragma unroll
    for (int mi = 0; mi < MF; ++mi)
#pragma unroll
        for (int ni = 0; ni < NF; ++ni) {
            int row = m0 + wm * (MF * 16) + mi * 16 + gq;
            int col = n0 + wn * (NF * 8) + ni * 8 + tq * 2;
#pragma unroll
            for (int hf = 0; hf < 2; ++hf) {
                int r = row + hf * 8;
                float v0 = acc[mi][ni][hf * 2 + 0] + bias[col];
                float v1 = acc[mi][ni][hf * 2 + 1] + bias[col + 1];
                *reinterpret_cast<float2*>(&g_Gin[(size_t)r * G4 + col]) =
                    make_float2(v0, v1);
            }
        }
}

// ------------------------- vocab GEMM: plain fp16, ldmatrix -----------------
constexpr int VS = 3;
__global__ void __launch_bounds__(256)
gemm_vocab(const uint32_t* __restrict__ A, const uint32_t* __restrict__ Bw,
           const float* __restrict__ bias, float* __restrict__ C) {
    constexpr int BM = 128, BN = 128, LDP = 20;
    constexpr int WMS = 2, WNS = 4;
    constexpr int MF = 4, NF = 4, KS = 2;
    constexpr int KT = HH / 32;                     // 32
    constexpr int ASW = BM * LDP;
    constexpr int BSW = BN * LDP;

    extern __shared__ uint32_t sv[];
    uint32_t* As = sv;
    uint32_t* Bs = sv + VS * ASW;

    const int tid = threadIdx.x, lane = tid & 31, warp = tid >> 5;
    const int wm = warp % WMS, wn = warp / WMS;
    const int gq = lane >> 2, tq = lane & 3;
    const int m0 = blockIdx.x * BM, n0 = blockIdx.y * BN;   // m fastest

    const int mmid = lane >> 3, rr = lane & 7;
    const int arow = (mmid & 1) * 8 + rr, acolw = (mmid >> 1) * 4;
    const int brow = (mmid >> 1) * 8 + rr, bcolw = (mmid & 1) * 4;
    const uint32_t Au = (uint32_t)__cvta_generic_to_shared(As);
    const uint32_t Bu = (uint32_t)__cvta_generic_to_shared(Bs);

    auto loadT = [&](int st, int kt) {
#pragma unroll
        for (int it = 0; it < 2; ++it) {
            int i = tid + it * 256;
            int r = i >> 2, cq = (i & 3) * 4;
            cpa16p(&As[st * ASW + r * LDP + cq],
                   &A[(size_t)(m0 + r) * HHP + kt * 16 + cq]);
            cpa16p(&Bs[st * BSW + r * LDP + cq],
                   &Bw[(size_t)(n0 + r) * HHP + kt * 16 + cq]);
        }
    };

    float acc[MF][NF][4] = {};

    loadT(0, 0); cpa_commit();
    loadT(1, 1); cpa_commit();

    for (int kt = 0; kt < KT; ++kt) {
        cpa_wait<1>();
        __syncthreads();
        if (kt + 2 < KT) loadT((kt + 2) % VS, kt + 2);
        cpa_commit();

        const uint32_t so = (kt % VS) * ASW * 4;
        const uint32_t sob = (kt % VS) * BSW * 4;
#pragma unroll
        for (int ks = 0; ks < KS; ++ks) {
            uint32_t af[MF][4], bq[2][4];
#pragma unroll
            for (int mi = 0; mi < MF; ++mi)
                ldsm_x4(af[mi], Au + so +
                        ((wm * 64 + mi * 16 + arow) * LDP + ks * 8 + acolw) * 4);
#pragma unroll
            for (int nb = 0; nb < 2; ++nb)
                ldsm_x4(bq[nb], Bu + sob +
                        ((wn * 32 + nb * 16 + brow) * LDP + ks * 8 + bcolw) * 4);
#pragma unroll
            for (int mi = 0; mi < MF; ++mi)
#pragma unroll
                for (int ni = 0; ni < NF; ++ni)
                    mma_fp16(acc[mi][ni], af[mi],
                             bq[ni >> 1][(ni & 1) * 2],
                             bq[ni >> 1][(ni & 1) * 2 + 1]);
        }
    }
    cpa_wait<0>();

#pragma unroll
    for (int mi = 0; mi < MF; ++mi)
#pragma unroll
        for (int ni = 0; ni < NF; ++ni) {
            int row = m0 + wm * (MF * 16) + mi * 16 + gq;
            int col = n0 + wn * (NF * 8) + ni * 8 + tq * 2;
#pragma unroll
            for (int hf = 0; hf < 2; ++hf) {
                int r = row + hf * 8;
                float v0 = acc[mi][ni][hf * 2 + 0] + bias[col];
                float v1 = acc[mi][ni][hf * 2 + 1] + bias[col + 1];
                int b = r & (BB - 1);
                int t = r >> 7;
                size_t o = ((size_t)b * (TT - 1) + t) * VOC + col;
                *reinterpret_cast<float2*>(&C[o]) = make_float2(v0, v1);
            }
        }
}

// ------------------------- persistent recurrence ----------------------------
// ONE kernel runs all 25 steps. W_hh hi/lo resident in SMEM (loaded once),
// c in registers, h double-buffered in global, spin grid-barrier per step.
constexpr int RW_LD = 516;            // W smem row stride (conflict-free ldsm)
constexpr int RP_ASW = 128 * 20;      // h stage words per half
constexpr int SM_RECP = (2 * 32 * RW_LD + 4 * RP_ASW) * 4;   // 173056 B

__global__ void __launch_bounds__(256)
rec_persist(const uint32_t* __restrict__ WHi, const uint32_t* __restrict__ WLo,
            const float* __restrict__ Gin,
            uint32_t* __restrict__ hHiA, uint32_t* __restrict__ hLoA,
            uint32_t* __restrict__ hHiB, uint32_t* __restrict__ hLoB,
            uint32_t* __restrict__ Hb) {
    constexpr int BM = 128, BN = 32, LDP = 20;
    constexpr int WMS = 4;
    constexpr int MF = 2, NF = 2, KS = 2, KT = 32;

    extern __shared__ uint32_t sp[];
    uint32_t* Whi = sp;                       // [32][516]
    uint32_t* Wlo = sp + 32 * RW_LD;
    uint32_t* AH  = sp + 2 * 32 * RW_LD;      // [2][128][20]
    uint32_t* AL  = AH + 2 * RP_ASW;
    __shared__ float Gt[BM][BN + 1];

    const int tid = threadIdx.x, lane = tid & 31, warp = tid >> 5;
    const int wm = warp % WMS, wn = warp / WMS;
    const int gq = lane >> 2, tq = lane & 3;
    const int n0 = blockIdx.x * BN;

    const int mmid = lane >> 3, rr = lane & 7;
    const int arow = (mmid & 1) * 8 + rr, acolw = (mmid >> 1) * 4;
    const int brow = (mmid >> 1) * 8 + rr, bcolw = (mmid & 1) * 4;
    const uint32_t AHu = (uint32_t)__cvta_generic_to_shared(AH);
    const uint32_t ALu = (uint32_t)__cvta_generic_to_shared(AL);
    const uint32_t WHu = (uint32_t)__cvta_generic_to_shared(Whi);
    const uint32_t WLu = (uint32_t)__cvta_generic_to_shared(Wlo);

    // ---- preload this CTA's W_hh slice (32 gate-cols x 1024) into SMEM ----
    for (int i = tid; i < 32 * 128; i += 256) {   // 128 x 16B chunks per row
        int r = i >> 7, cw = (i & 127) * 4;
        cpa16p(&Whi[r * RW_LD + cw], &WHi[(size_t)(n0 + r) * HHP + cw]);
        cpa16p(&Wlo[r * RW_LD + cw], &WLo[(size_t)(n0 + r) * HHP + cw]);
    }
    cpa_commit(); cpa_wait<0>();
    __syncthreads();

    float creg[8];
#pragma unroll
    for (int u = 0; u < 8; ++u) creg[u] = 0.f;

    for (int t = 0; t < TT; ++t) {
        float acc[MF][NF][4] = {};

        if (t > 0) {
            const uint32_t* hHi = ((t & 1) == 0) ? hHiB : hHiA;  // prev buf
            const uint32_t* hLo = ((t & 1) == 0) ? hLoB : hLoA;
            auto loadA = [&](int st, int kt) {
#pragma unroll
                for (int it = 0; it < 2; ++it) {
                    int i = tid + it * 256;
                    int r = i >> 2, cq = (i & 3) * 4;
                    cpa16p(&AH[st * RP_ASW + r * LDP + cq],
                           &hHi[(size_t)r * HHP + kt * 16 + cq]);
                    cpa16p(&AL[st * RP_ASW + r * LDP + cq],
                           &hLo[(size_t)r * HHP + kt * 16 + cq]);
                }
            };
            loadA(0, 0); cpa_commit();

            for (int kt = 0; kt < KT; ++kt) {
                cpa_wait<0>();
                __syncthreads();
                if (kt + 1 < KT) loadA((kt + 1) & 1, kt + 1);
                cpa_commit();

                const uint32_t so = (kt & 1) * RP_ASW * 4;
#pragma unroll
                for (int ks = 0; ks < KS; ++ks) {
                    uint32_t ah[MF][4], al[MF][4], bh[4], bl[4];
#pragma unroll
                    for (int mi = 0; mi < MF; ++mi) {
                        uint32_t off = ((wm * 32 + mi * 16 + arow) * LDP +
                                        ks * 8 + acolw) * 4;
                        ldsm_x4(ah[mi], AHu + so + off);
                        ldsm_x4(al[mi], ALu + so + off);
                    }
                    {
                        uint32_t off = ((wn * 16 + brow) * RW_LD +
                                        kt * 16 + ks * 8 + bcolw) * 4;
                        ldsm_x4(bh, WHu + off);
                        ldsm_x4(bl, WLu + off);
                    }
#pragma unroll
                    for (int mi = 0; mi < MF; ++mi)
#pragma unroll
                        for (int ni = 0; ni < NF; ++ni) {
                            mma_bf16(acc[mi][ni], ah[mi],
                                     bh[ni * 2], bh[ni * 2 + 1]);
                            mma_bf16(acc[mi][ni], ah[mi],
                                     bl[ni * 2], bl[ni * 2 + 1]);
                            mma_bf16(acc[mi][ni], al[mi],
                                     bh[ni * 2], bh[ni * 2 + 1]);
                        }
                }
            }
            cpa_wait<0>();
            __syncthreads();
        }

        // ---- epilogue: stage gates (+Gin[t]) in SMEM, fused LSTM cell ----
        const float* GinT = Gin + (size_t)t * BB * G4;
#pragma unroll
        for (int mi = 0; mi < MF; ++mi)
#pragma unroll
            for (int ni = 0; ni < NF; ++ni)
#pragma unroll
                for (int hf = 0; hf < 2; ++hf) {
                    int row = wm * (MF * 16) + mi * 16 + gq + hf * 8;
                    int col = wn * (NF * 8) + ni * 8 + tq * 2;
                    float2 ad = *reinterpret_cast<const float2*>(
                        &GinT[(size_t)row * G4 + n0 + col]);
                    Gt[row][col]     = acc[mi][ni][hf * 2 + 0] + ad.x;
                    Gt[row][col + 1] = acc[mi][ni][hf * 2 + 1] + ad.y;
                }
        __syncthreads();

        if (tid < BM) {
            int row = tid;
            int jbase = n0 >> 2;
            uint32_t* hOutHi = (t & 1) ? hHiB : hHiA;
            uint32_t* hOutLo = (t & 1) ? hLoB : hLoA;
            __nv_bfloat16* oh = reinterpret_cast<__nv_bfloat16*>(hOutHi);
            __nv_bfloat16* ol = reinterpret_cast<__nv_bfloat16*>(hOutLo);
            __half* HbH = reinterpret_cast<__half*>(Hb);
#pragma unroll
            for (int u = 0; u < 8; ++u) {
                float gi = Gt[row][u * 4 + 0];
                float gf = Gt[row][u * 4 + 1];
                float gg = Gt[row][u * 4 + 2];
                float go = Gt[row][u * 4 + 3];
                float cn = sigm(gf) * creg[u] + sigm(gi) * tanhf(gg);
                float hn = sigm(go) * tanhf(cn);
                creg[u] = cn;
                int ci = row * HH + jbase + u;
                __nv_bfloat16 hb = __float2bfloat16_rn(hn);
                oh[ci] = hb;
                ol[ci] = __float2bfloat16_rn(hn - __bfloat162float(hb));
                if (t > 0)
                    HbH[(size_t)(t - 1) * BB * HH + ci] = __float2half_rn(hn);
            }
        }

        if (t + 1 < TT) grid_bar(128u * (unsigned)(t + 1));
    }
}

// ------------------------- prep kernels -------------------------------------
__global__ void prep_bias_k(const float* __restrict__ bi,
                            const float* __restrict__ bh, float* out) {
    int p = blockIdx.x * blockDim.x + threadIdx.x;
    if (p >= G4) return;
    int src = (p & 3) * HH + (p >> 2);
    out[p] = bi[src] + bh[src];
}

__device__ __forceinline__ void split_pair(float v0, float v1,
                                           uint32_t& hi, uint32_t& lo) {
    __nv_bfloat16 h0 = __float2bfloat16_rn(v0);
    __nv_bfloat16 h1 = __float2bfloat16_rn(v1);
    hi = pack_bf(v0, v1);
    lo = pack_bf(v0 - __bfloat162float(h0), v1 - __bfloat162float(h1));
}

__global__ void prep_Wih_k(const float* __restrict__ W,
                           uint32_t* __restrict__ hi, uint32_t* __restrict__ lo) {
    int i = blockIdx.x * blockDim.x + threadIdx.x;
    if (i >= G4 * KINP) return;
    int p = i / KINP, kp = i % KINP;
    int src = (p & 3) * HH + (p >> 2);
    int k0 = 2 * kp, k1 = 2 * kp + 1;
    float v0 = (k0 < KRAW) ? W[(size_t)src * KRAW + k0] : 0.f;
    float v1 = (k1 < KRAW) ? W[(size_t)src * KRAW + k1] : 0.f;
    split_pair(v0, v1, hi[i], lo[i]);
}

__global__ void prep_Whh_k(const float* __restrict__ W,
                           uint32_t* __restrict__ hi, uint32_t* __restrict__ lo) {
    int i = blockIdx.x * blockDim.x + threadIdx.x;
    if (i >= G4 * HHP) return;
    int p = i / HHP, kp = i % HHP;
    int src = (p & 3) * HH + (p >> 2);
    float v0 = W[(size_t)src * HH + 2 * kp];
    float v1 = W[(size_t)src * HH + 2 * kp + 1];
    split_pair(v0, v1, hi[i], lo[i]);
}

__global__ void prep_fcnW_k(const float* __restrict__ W,
                            uint32_t* __restrict__ Wp) {
    size_t i = (size_t)blockIdx.x * blockDim.x + threadIdx.x;  // 2-pair index
    if (i * 2 >= (size_t)VOC * HHP) return;
    float4 v = *reinterpret_cast<const float4*>(&W[i * 4]);
    __half2 p0 = __floats2half2_rn(v.x, v.y);
    __half2 p1 = __floats2half2_rn(v.z, v.w);
    *reinterpret_cast<uint2*>(&Wp[i * 2]) =
        make_uint2(*reinterpret_cast<uint32_t*>(&p0),
                   *reinterpret_cast<uint32_t*>(&p1));
}

__device__ __forceinline__ float xval(const float* feat, const int* caps,
                                      const float* emb, int t, int b, int k) {
    if (k < EE) {
        int tok = (t == 0) ? 1 : caps[b * TT + (t - 1)];
        return emb[(size_t)tok * EE + k];
    }
    if (k < KRAW) return feat[b * ENC + (k - EE)];
    return 0.f;
}

__global__ void prep_X_k(const float* __restrict__ feat,
                         const int* __restrict__ caps,
                         const float* __restrict__ emb,
                         uint32_t* __restrict__ hi, uint32_t* __restrict__ lo) {
    int i = blockIdx.x * blockDim.x + threadIdx.x;
    if (i >= MX * KINP) return;
    int r = i / KINP, kp = i % KINP;
    int t = r / BB, b = r % BB;
    float v0 = xval(feat, caps, emb, t, b, 2 * kp);
    float v1 = xval(feat, caps, emb, t, b, 2 * kp + 1);
    split_pair(v0, v1, hi[i], lo[i]);
}

__global__ void zero_init_k() {
    if (blockIdx.x == 0 && threadIdx.x == 0) g_barctr = 0u;
}

// ------------------------- launch -------------------------------------------
extern "C" void kernel_launch(void* const* d_in, const int* in_sizes, int n_in,
                              void* d_out, int out_size) {
    const float* features = (const float*)d_in[0];
    const int*   captions = (const int*)d_in[1];
    const float* emb_W    = (const float*)d_in[2];
    const float* W_ih     = (const float*)d_in[3];
    const float* W_hh     = (const float*)d_in[4];
    const float* b_ih     = (const float*)d_in[5];
    const float* b_hh     = (const float*)d_in[6];
    // d_in[7..12]: attention weights — dead (softmax over a single element)
    const float* fcn_W    = (const float*)d_in[13];
    const float* fcn_b    = (const float*)d_in[14];
    float* out = (float*)d_out;

    float *bias, *Gin;
    uint32_t *Xhi, *Xlo, *WihHi, *WihLo, *WhhHi, *WhhLo, *fWp;
    uint32_t *hHiA, *hHiB, *hLoA, *hLoB, *Hb;
    cudaGetSymbolAddress((void**)&Xhi, g_Xhi);
    cudaGetSymbolAddress((void**)&Xlo, g_Xlo);
    cudaGetSymbolAddress((void**)&WihHi, g_WihHi);
    cudaGetSymbolAddress((void**)&WihLo, g_WihLo);
    cudaGetSymbolAddress((void**)&bias, g_bias);
    cudaGetSymbolAddress((void**)&Gin, g_Gin);
    cudaGetSymbolAddress((void**)&WhhHi, g_WhhHi);
    cudaGetSymbolAddress((void**)&WhhLo, g_WhhLo);
    cudaGetSymbolAddress((void**)&fWp, g_fWp);
    cudaGetSymbolAddress((void**)&hHiA, g_hHiA);
    cudaGetSymbolAddress((void**)&hHiB, g_hHiB);
    cudaGetSymbolAddress((void**)&hLoA, g_hLoA);
    cudaGetSymbolAddress((void**)&hLoB, g_hLoB);
    cudaGetSymbolAddress((void**)&Hb, g_Hb);

    constexpr int SM_IN  = (4 * 128 * 20 + 4 * 128 * 20) * 4;   // 81920
    constexpr int SM_VOC = VS * (128 * 20 + 128 * 20) * 4;      // 61440
    cudaFuncSetAttribute(gemm_in,
                         cudaFuncAttributeMaxDynamicSharedMemorySize, SM_IN);
    cudaFuncSetAttribute(gemm_vocab,
                         cudaFuncAttributeMaxDynamicSharedMemorySize, SM_VOC);
    cudaFuncSetAttribute(rec_persist,
                         cudaFuncAttributeMaxDynamicSharedMemorySize, SM_RECP);

    // prep
    prep_bias_k<<<(G4 + 255) / 256, 256>>>(b_ih, b_hh, bias);
    prep_Wih_k<<<(G4 * KINP + 255) / 256, 256>>>(W_ih, WihHi, WihLo);
    prep_Whh_k<<<(G4 * HHP + 255) / 256, 256>>>(W_hh, WhhHi, WhhLo);
    prep_fcnW_k<<<((int)((size_t)VOC * HHP / 2) + 255) / 256, 256>>>(fcn_W, fWp);
    prep_X_k<<<(MX * KINP + 255) / 256, 256>>>(features, captions, emb_W,
                                               Xhi, Xlo);
    zero_init_k<<<1, 32>>>();

    // input projection for all timesteps (permuted gate layout, bf16 split)
    gemm_in<<<dim3(G4 / 128, MX / 128), 256, SM_IN>>>(Xhi, Xlo, WihHi, WihLo,
                                                      bias);

    // full 25-step LSTM in ONE persistent kernel (128 CTAs, all resident)
    rec_persist<<<G4 / 32, 256, SM_RECP>>>(WhhHi, WhhLo, Gin,
                                           hHiA, hLoA, hHiB, hLoB, Hb);

    // batched vocab projection (plain fp16, ldmatrix, m-fastest grid)
    gemm_vocab<<<dim3(MO / 128, VOC / 128), 256, SM_VOC>>>(Hb, fWp, fcn_b,
                                                           out);
}

// round 11
// speedup vs baseline: 3.1167x; 1.0419x over previous
#include <cuda_runtime.h>
#include <cuda_bf16.h>
#include <cuda_fp16.h>
#include <cstdint>

// ---------------------------------------------------------------------------
// DecoderRNNWithAttention — GB300 sm_103a, round 10
//  * attention provably dead (softmax over 1 element) -> context == features
//  * vocab GEMM: BM=128 x BN=256 tiles (25% less L2 operand traffic, 2x mma
//    per B-ldsm), plain fp16 m16n8k16, 3-stage cp.async, m-fastest grid
//  * persistent recurrence: BK doubled to 32 pairs (KT=16) -> half the
//    exposed L2 latencies per step; W_hh SMEM-resident, c in registers
//  * ldmatrix.x4 fragment loads everywhere
// ---------------------------------------------------------------------------

constexpr int BB  = 128;
constexpr int TT  = 25;
constexpr int EE  = 512;
constexpr int HH  = 1024;
constexpr int ENC = 400;
constexpr int VOC = 32000;
constexpr int KRAW = EE + ENC;      // 912
constexpr int KIN  = 928;           // padded to /32
constexpr int KINP = KIN / 2;       // 464 pairs
constexpr int HHP  = HH / 2;        // 512 pairs
constexpr int G4   = 4 * HH;        // 4096
constexpr int MX   = TT * BB;       // 3200
constexpr int MO   = (TT - 1) * BB; // 3072

// ------------------------- scratch (static, no cudaMalloc) -----------------
__device__ uint32_t g_Xhi[MX * KINP];            // bf16x2 pairs
__device__ uint32_t g_Xlo[MX * KINP];
__device__ uint32_t g_WihHi[G4 * KINP];
__device__ uint32_t g_WihLo[G4 * KINP];
__device__ float    g_bias[G4];
__device__ float    g_Gin[(size_t)MX * G4];
__device__ uint32_t g_WhhHi[G4 * HHP];
__device__ uint32_t g_WhhLo[G4 * HHP];
__device__ uint32_t g_fWp[(size_t)VOC * HHP];    // fcn_W as fp16x2 pairs
__device__ uint32_t g_hHiA[BB * HHP], g_hHiB[BB * HHP];   // h as bf16x2
__device__ uint32_t g_hLoA[BB * HHP], g_hLoB[BB * HHP];
__device__ uint32_t g_Hb[(size_t)MO * HHP];      // hidden states as fp16x2
__device__ unsigned g_barctr;                    // grid barrier counter

// ------------------------- helpers -----------------------------------------
__device__ __forceinline__ uint32_t pack_bf(float a, float b) {
    __nv_bfloat162 t = __floats2bfloat162_rn(a, b);
    return *reinterpret_cast<uint32_t*>(&t);
}

__device__ __forceinline__ void mma_bf16(float (&d)[4], const uint32_t (&a)[4],
                                         uint32_t b0, uint32_t b1) {
    asm volatile(
        "mma.sync.aligned.m16n8k16.row.col.f32.bf16.bf16.f32 "
        "{%0,%1,%2,%3},{%4,%5,%6,%7},{%8,%9},{%0,%1,%2,%3};"
        : "+f"(d[0]), "+f"(d[1]), "+f"(d[2]), "+f"(d[3])
        : "r"(a[0]), "r"(a[1]), "r"(a[2]), "r"(a[3]), "r"(b0), "r"(b1));
}

__device__ __forceinline__ void mma_fp16(float (&d)[4], const uint32_t (&a)[4],
                                         uint32_t b0, uint32_t b1) {
    asm volatile(
        "mma.sync.aligned.m16n8k16.row.col.f32.f16.f16.f32 "
        "{%0,%1,%2,%3},{%4,%5,%6,%7},{%8,%9},{%0,%1,%2,%3};"
        : "+f"(d[0]), "+f"(d[1]), "+f"(d[2]), "+f"(d[3])
        : "r"(a[0]), "r"(a[1]), "r"(a[2]), "r"(a[3]), "r"(b0), "r"(b1));
}

__device__ __forceinline__ void ldsm_x4(uint32_t (&r)[4], uint32_t addr) {
    asm volatile(
        "ldmatrix.sync.aligned.m8n8.x4.shared.b16 {%0,%1,%2,%3}, [%4];"
        : "=r"(r[0]), "=r"(r[1]), "=r"(r[2]), "=r"(r[3]) : "r"(addr));
}

__device__ __forceinline__ void cpa16p(void* s, const void* g) {
    uint32_t sa = (uint32_t)__cvta_generic_to_shared(s);
    asm volatile("cp.async.cg.shared.global [%0], [%1], 16;" ::"r"(sa), "l"(g));
}
__device__ __forceinline__ void cpa_commit() {
    asm volatile("cp.async.commit_group;");
}
template <int N> __device__ __forceinline__ void cpa_wait() {
    asm volatile("cp.async.wait_group %0;" ::"n"(N));
}

__device__ __forceinline__ float sigm(float x) { return 1.f / (1.f + expf(-x)); }

// all-threads fence, then thread0 arrives + spins; safe: 128 CTAs all resident
__device__ __forceinline__ void grid_bar(unsigned target) {
    __threadfence();
    __syncthreads();
    if (threadIdx.x == 0) {
        atomicAdd(&g_barctr, 1u);
        volatile unsigned* p = &g_barctr;
        while (*p < target) {}
    }
    __syncthreads();
    __threadfence();
}

// ------------------------- input GEMM (bf16 3-term split, ldmatrix) ---------
__global__ void __launch_bounds__(256)
gemm_in(const uint32_t* __restrict__ Ahi, const uint32_t* __restrict__ Alo,
        const uint32_t* __restrict__ Bhi, const uint32_t* __restrict__ Blo,
        const float* __restrict__ bias) {
    constexpr int BM = 128, BN = 128, LDP = 20;
    constexpr int WMS = 2, WNS = 4;
    constexpr int MF = 4, NF = 4, KS = 2;
    constexpr int KT = KIN / 32;                    // 29
    constexpr int ASW = BM * LDP;
    constexpr int BSW = BN * LDP;

    extern __shared__ uint32_t sm[];
    uint32_t* AHs = sm;
    uint32_t* ALs = sm + 2 * ASW;
    uint32_t* BHs = sm + 4 * ASW;
    uint32_t* BLs = sm + 4 * ASW + 2 * BSW;

    const int tid = threadIdx.x, lane = tid & 31, warp = tid >> 5;
    const int wm = warp % WMS, wn = warp / WMS;
    const int gq = lane >> 2, tq = lane & 3;
    const int m0 = blockIdx.y * BM, n0 = blockIdx.x * BN;

    const int mmid = lane >> 3, rr = lane & 7;
    const int arow = (mmid & 1) * 8 + rr, acolw = (mmid >> 1) * 4;
    const int brow = (mmid >> 1) * 8 + rr, bcolw = (mmid & 1) * 4;
    const uint32_t AHu = (uint32_t)__cvta_generic_to_shared(AHs);
    const uint32_t ALu = (uint32_t)__cvta_generic_to_shared(ALs);
    const uint32_t BHu = (uint32_t)__cvta_generic_to_shared(BHs);
    const uint32_t BLu = (uint32_t)__cvta_generic_to_shared(BLs);

    auto loadT = [&](int st, int kt) {
#pragma unroll
        for (int it = 0; it < 2; ++it) {
            int i = tid + it * 256;
            int r = i >> 2, cq = (i & 3) * 4;
            cpa16p(&AHs[st * ASW + r * LDP + cq],
                   &Ahi[(size_t)(m0 + r) * KINP + kt * 16 + cq]);
            cpa16p(&ALs[st * ASW + r * LDP + cq],
                   &Alo[(size_t)(m0 + r) * KINP + kt * 16 + cq]);
            cpa16p(&BHs[st * BSW + r * LDP + cq],
                   &Bhi[(size_t)(n0 + r) * KINP + kt * 16 + cq]);
            cpa16p(&BLs[st * BSW + r * LDP + cq],
                   &Blo[(size_t)(n0 + r) * KINP + kt * 16 + cq]);
        }
    };

    float acc[MF][NF][4] = {};

    loadT(0, 0); cpa_commit();

    for (int kt = 0; kt < KT; ++kt) {
        cpa_wait<0>();
        __syncthreads();
        if (kt + 1 < KT) loadT((kt + 1) & 1, kt + 1);
        cpa_commit();

        const uint32_t so = (kt & 1) * ASW * 4;
        const uint32_t sob = (kt & 1) * BSW * 4;
#pragma unroll
        for (int ks = 0; ks < KS; ++ks) {
            uint32_t ah[MF][4], al[MF][4], bh[2][4], bl[2][4];
#pragma unroll
            for (int mi = 0; mi < MF; ++mi) {
                uint32_t off = ((wm * 64 + mi * 16 + arow) * LDP +
                                ks * 8 + acolw) * 4;
                ldsm_x4(ah[mi], AHu + so + off);
                ldsm_x4(al[mi], ALu + so + off);
            }
#pragma unroll
            for (int nb = 0; nb < 2; ++nb) {
                uint32_t off = ((wn * 32 + nb * 16 + brow) * LDP +
                                ks * 8 + bcolw) * 4;
                ldsm_x4(bh[nb], BHu + sob + off);
                ldsm_x4(bl[nb], BLu + sob + off);
            }
#pragma unroll
            for (int mi = 0; mi < MF; ++mi)
#pragma unroll
                for (int ni = 0; ni < NF; ++ni) {
                    uint32_t h0 = bh[ni >> 1][(ni & 1) * 2];
                    uint32_t h1 = bh[ni >> 1][(ni & 1) * 2 + 1];
                    uint32_t l0 = bl[ni >> 1][(ni & 1) * 2];
                    uint32_t l1 = bl[ni >> 1][(ni & 1) * 2 + 1];
                    mma_bf16(acc[mi][ni], ah[mi], h0, h1);
                    mma_bf16(acc[mi][ni], ah[mi], l0, l1);
                    mma_bf16(acc[mi][ni], al[mi], h0, h1);
                }
        }
    }
    cpa_wait<0>();

#pragma unroll
    for (int mi = 0; mi < MF; ++mi)
#pragma unroll
        for (int ni = 0; ni < NF; ++ni) {
            int row = m0 + wm * (MF * 16) + mi * 16 + gq;
            int col = n0 + wn * (NF * 8) + ni * 8 + tq * 2;
#pragma unroll
            for (int hf = 0; hf < 2; ++hf) {
                int r = row + hf * 8;
                float v0 = acc[mi][ni][hf * 2 + 0] + bias[col];
                float v1 = acc[mi][ni][hf * 2 + 1] + bias[col + 1];
                *reinterpret_cast<float2*>(&g_Gin[(size_t)r * G4 + col]) =
                    make_float2(v0, v1);
            }
        }
}

// ------------------------- vocab GEMM: fp16, BM=128 x BN=256 ---------------
constexpr int VS = 3;
__global__ void __launch_bounds__(256)
gemm_vocab(const uint32_t* __restrict__ A, const uint32_t* __restrict__ Bw,
           const float* __restrict__ bias, float* __restrict__ C) {
    constexpr int BM = 128, BN = 256, LDP = 20;
    constexpr int WMS = 2, WNS = 4;
    constexpr int MF = 4, NF = 8, KS = 2;
    constexpr int KT = HH / 32;                     // 32
    constexpr int ASW = BM * LDP;                   // 2560
    constexpr int BSW = BN * LDP;                   // 5120

    extern __shared__ uint32_t sv[];
    uint32_t* As = sv;
    uint32_t* Bs = sv + VS * ASW;

    const int tid = threadIdx.x, lane = tid & 31, warp = tid >> 5;
    const int wm = warp % WMS, wn = warp / WMS;
    const int gq = lane >> 2, tq = lane & 3;
    const int m0 = blockIdx.x * BM, n0 = blockIdx.y * BN;   // m fastest

    const int mmid = lane >> 3, rr = lane & 7;
    const int arow = (mmid & 1) * 8 + rr, acolw = (mmid >> 1) * 4;
    const int brow = (mmid >> 1) * 8 + rr, bcolw = (mmid & 1) * 4;
    const uint32_t Au = (uint32_t)__cvta_generic_to_shared(As);
    const uint32_t Bu = (uint32_t)__cvta_generic_to_shared(Bs);

    auto loadT = [&](int st, int kt) {
#pragma unroll
        for (int it = 0; it < 2; ++it) {            // A: 512 chunks
            int i = tid + it * 256;
            int r = i >> 2, cq = (i & 3) * 4;
            cpa16p(&As[st * ASW + r * LDP + cq],
                   &A[(size_t)(m0 + r) * HHP + kt * 16 + cq]);
        }
#pragma unroll
        for (int it = 0; it < 4; ++it) {            // B: 1024 chunks
            int i = tid + it * 256;
            int r = i >> 2, cq = (i & 3) * 4;
            cpa16p(&Bs[st * BSW + r * LDP + cq],
                   &Bw[(size_t)(n0 + r) * HHP + kt * 16 + cq]);
        }
    };

    float acc[MF][NF][4] = {};

    loadT(0, 0); cpa_commit();
    loadT(1, 1); cpa_commit();

    for (int kt = 0; kt < KT; ++kt) {
        cpa_wait<1>();
        __syncthreads();
        if (kt + 2 < KT) loadT((kt + 2) % VS, kt + 2);
        cpa_commit();

        const uint32_t so = (kt % VS) * ASW * 4;
        const uint32_t sob = (kt % VS) * BSW * 4;
#pragma unroll
        for (int ks = 0; ks < KS; ++ks) {
            uint32_t af[MF][4], bq[4][4];
#pragma unroll
            for (int mi = 0; mi < MF; ++mi)
                ldsm_x4(af[mi], Au + so +
                        ((wm * 64 + mi * 16 + arow) * LDP + ks * 8 + acolw) * 4);
#pragma unroll
            for (int nb = 0; nb < 4; ++nb)
                ldsm_x4(bq[nb], Bu + sob +
                        ((wn * 64 + nb * 16 + brow) * LDP + ks * 8 + bcolw) * 4);
#pragma unroll
            for (int mi = 0; mi < MF; ++mi)
#pragma unroll
                for (int ni = 0; ni < NF; ++ni)
                    mma_fp16(acc[mi][ni], af[mi],
                             bq[ni >> 1][(ni & 1) * 2],
                             bq[ni >> 1][(ni & 1) * 2 + 1]);
        }
    }
    cpa_wait<0>();

#pragma unroll
    for (int mi = 0; mi < MF; ++mi)
#pragma unroll
        for (int ni = 0; ni < NF; ++ni) {
            int row = m0 + wm * (MF * 16) + mi * 16 + gq;
            int col = n0 + wn * 64 + ni * 8 + tq * 2;
#pragma unroll
            for (int hf = 0; hf < 2; ++hf) {
                int r = row + hf * 8;
                float v0 = acc[mi][ni][hf * 2 + 0] + bias[col];
                float v1 = acc[mi][ni][hf * 2 + 1] + bias[col + 1];
                int b = r & (BB - 1);
                int t = r >> 7;
                size_t o = ((size_t)b * (TT - 1) + t) * VOC + col;
                *reinterpret_cast<float2*>(&C[o]) = make_float2(v0, v1);
            }
        }
}

// ------------------------- persistent recurrence ----------------------------
// ONE kernel runs all 25 steps. W_hh hi/lo resident in SMEM (loaded once),
// c in registers, h double-buffered in global, spin grid-barrier per step.
// BK = 32 pairs (64 elements) per k-tile -> KT=16, half the exposed waits.
constexpr int RW_LD = 516;            // W smem row stride (conflict-free ldsm)
constexpr int RLDP  = 36;             // h stage row stride (32 pairs + 4 pad)
constexpr int RP_ASW = 128 * RLDP;    // 4608 words per h half-stage
constexpr int SM_RECP = (2 * 32 * RW_LD + 4 * RP_ASW) * 4;   // 205824 B

__global__ void __launch_bounds__(256)
rec_persist(const uint32_t* __restrict__ WHi, const uint32_t* __restrict__ WLo,
            const float* __restrict__ Gin,
            uint32_t* __restrict__ hHiA, uint32_t* __restrict__ hLoA,
            uint32_t* __restrict__ hHiB, uint32_t* __restrict__ hLoB,
            uint32_t* __restrict__ Hb) {
    constexpr int BM = 128, BN = 32;
    constexpr int WMS = 4;
    constexpr int MF = 2, NF = 2, KS = 4, KT = 16;

    extern __shared__ uint32_t sp[];
    uint32_t* Whi = sp;                       // [32][516]
    uint32_t* Wlo = sp + 32 * RW_LD;
    uint32_t* AH  = sp + 2 * 32 * RW_LD;      // [2][128][36]
    uint32_t* AL  = AH + 2 * RP_ASW;
    __shared__ float Gt[BM][BN + 1];

    const int tid = threadIdx.x, lane = tid & 31, warp = tid >> 5;
    const int wm = warp % WMS, wn = warp / WMS;
    const int gq = lane >> 2, tq = lane & 3;
    const int n0 = blockIdx.x * BN;

    const int mmid = lane >> 3, rr = lane & 7;
    const int arow = (mmid & 1) * 8 + rr, acolw = (mmid >> 1) * 4;
    const int brow = (mmid >> 1) * 8 + rr, bcolw = (mmid & 1) * 4;
    const uint32_t AHu = (uint32_t)__cvta_generic_to_shared(AH);
    const uint32_t ALu = (uint32_t)__cvta_generic_to_shared(AL);
    const uint32_t WHu = (uint32_t)__cvta_generic_to_shared(Whi);
    const uint32_t WLu = (uint32_t)__cvta_generic_to_shared(Wlo);

    // ---- preload this CTA's W_hh slice (32 gate-cols x 1024) into SMEM ----
    for (int i = tid; i < 32 * 128; i += 256) {   // 128 x 16B chunks per row
        int r = i >> 7, cw = (i & 127) * 4;
        cpa16p(&Whi[r * RW_LD + cw], &WHi[(size_t)(n0 + r) * HHP + cw]);
        cpa16p(&Wlo[r * RW_LD + cw], &WLo[(size_t)(n0 + r) * HHP + cw]);
    }
    cpa_commit(); cpa_wait<0>();
    __syncthreads();

    float creg[8];
#pragma unroll
    for (int u = 0; u < 8; ++u) creg[u] = 0.f;

    for (int t = 0; t < TT; ++t) {
        float acc[MF][NF][4] = {};

        if (t > 0) {
            const uint32_t* hHi = ((t & 1) == 0) ? hHiB : hHiA;  // prev buf
            const uint32_t* hLo = ((t & 1) == 0) ? hLoB : hLoA;
            auto loadA = [&](int st, int kt) {
#pragma unroll
                for (int it = 0; it < 4; ++it) {   // 1024 chunks per half
                    int i = tid + it * 256;
                    int r = i >> 3, cq = (i & 7) * 4;
                    cpa16p(&AH[st * RP_ASW + r * RLDP + cq],
                           &hHi[(size_t)r * HHP + kt * 32 + cq]);
                    cpa16p(&AL[st * RP_ASW + r * RLDP + cq],
                           &hLo[(size_t)r * HHP + kt * 32 + cq]);
                }
            };
            loadA(0, 0); cpa_commit();

            for (int kt = 0; kt < KT; ++kt) {
                cpa_wait<0>();
                __syncthreads();
                if (kt + 1 < KT) loadA((kt + 1) & 1, kt + 1);
                cpa_commit();

                const uint32_t so = (kt & 1) * RP_ASW * 4;
#pragma unroll
                for (int ks = 0; ks < KS; ++ks) {
                    uint32_t ah[MF][4], al[MF][4], bh[4], bl[4];
#pragma unroll
                    for (int mi = 0; mi < MF; ++mi) {
                        uint32_t off = ((wm * 32 + mi * 16 + arow) * RLDP +
                                        ks * 8 + acolw) * 4;
                        ldsm_x4(ah[mi], AHu + so + off);
                        ldsm_x4(al[mi], ALu + so + off);
                    }
                    {
                        uint32_t off = ((wn * 16 + brow) * RW_LD +
                                        kt * 32 + ks * 8 + bcolw) * 4;
                        ldsm_x4(bh, WHu + off);
                        ldsm_x4(bl, WLu + off);
                    }
#pragma unroll
                    for (int mi = 0; mi < MF; ++mi)
#pragma unroll
                        for (int ni = 0; ni < NF; ++ni) {
                            mma_bf16(acc[mi][ni], ah[mi],
                                     bh[ni * 2], bh[ni * 2 + 1]);
                            mma_bf16(acc[mi][ni], ah[mi],
                                     bl[ni * 2], bl[ni * 2 + 1]);
                            mma_bf16(acc[mi][ni], al[mi],
                                     bh[ni * 2], bh[ni * 2 + 1]);
                        }
                }
            }
            cpa_wait<0>();
            __syncthreads();
        }

        // ---- epilogue: stage gates (+Gin[t]) in SMEM, fused LSTM cell ----
        const float* GinT = Gin + (size_t)t * BB * G4;
#pragma unroll
        for (int mi = 0; mi < MF; ++mi)
#pragma unroll
            for (int ni = 0; ni < NF; ++ni)
#pragma unroll
                for (int hf = 0; hf < 2; ++hf) {
                    int row = wm * (MF * 16) + mi * 16 + gq + hf * 8;
                    int col = wn * (NF * 8) + ni * 8 + tq * 2;
                    float2 ad = *reinterpret_cast<const float2*>(
                        &GinT[(size_t)row * G4 + n0 + col]);
                    Gt[row][col]     = acc[mi][ni][hf * 2 + 0] + ad.x;
                    Gt[row][col + 1] = acc[mi][ni][hf * 2 + 1] + ad.y;
                }
        __syncthreads();

        if (tid < BM) {
            int row = tid;
            int jbase = n0 >> 2;
            uint32_t* hOutHi = (t & 1) ? hHiB : hHiA;
            uint32_t* hOutLo = (t & 1) ? hLoB : hLoA;
            __nv_bfloat16* oh = reinterpret_cast<__nv_bfloat16*>(hOutHi);
            __nv_bfloat16* ol = reinterpret_cast<__nv_bfloat16*>(hOutLo);
            __half* HbH = reinterpret_cast<__half*>(Hb);
#pragma unroll
            for (int u = 0; u < 8; ++u) {
                float gi = Gt[row][u * 4 + 0];
                float gf = Gt[row][u * 4 + 1];
                float gg = Gt[row][u * 4 + 2];
                float go = Gt[row][u * 4 + 3];
                float cn = sigm(gf) * creg[u] + sigm(gi) * tanhf(gg);
                float hn = sigm(go) * tanhf(cn);
                creg[u] = cn;
                int ci = row * HH + jbase + u;
                __nv_bfloat16 hb = __float2bfloat16_rn(hn);
                oh[ci] = hb;
                ol[ci] = __float2bfloat16_rn(hn - __bfloat162float(hb));
                if (t > 0)
                    HbH[(size_t)(t - 1) * BB * HH + ci] = __float2half_rn(hn);
            }
        }

        if (t + 1 < TT) grid_bar(128u * (unsigned)(t + 1));
    }
}

// ------------------------- prep kernels -------------------------------------
__global__ void prep_bias_k(const float* __restrict__ bi,
                            const float* __restrict__ bh, float* out) {
    int p = blockIdx.x * blockDim.x + threadIdx.x;
    if (p >= G4) return;
    int src = (p & 3) * HH + (p >> 2);
    out[p] = bi[src] + bh[src];
}

__device__ __forceinline__ void split_pair(float v0, float v1,
                                           uint32_t& hi, uint32_t& lo) {
    __nv_bfloat16 h0 = __float2bfloat16_rn(v0);
    __nv_bfloat16 h1 = __float2bfloat16_rn(v1);
    hi = pack_bf(v0, v1);
    lo = pack_bf(v0 - __bfloat162float(h0), v1 - __bfloat162float(h1));
}

__global__ void prep_Wih_k(const float* __restrict__ W,
                           uint32_t* __restrict__ hi, uint32_t* __restrict__ lo) {
    int i = blockIdx.x * blockDim.x + threadIdx.x;
    if (i >= G4 * KINP) return;
    int p = i / KINP, kp = i % KINP;
    int src = (p & 3) * HH + (p >> 2);
    int k0 = 2 * kp, k1 = 2 * kp + 1;
    float v0 = (k0 < KRAW) ? W[(size_t)src * KRAW + k0] : 0.f;
    float v1 = (k1 < KRAW) ? W[(size_t)src * KRAW + k1] : 0.f;
    split_pair(v0, v1, hi[i], lo[i]);
}

__global__ void prep_Whh_k(const float* __restrict__ W,
                           uint32_t* __restrict__ hi, uint32_t* __restrict__ lo) {
    int i = blockIdx.x * blockDim.x + threadIdx.x;
    if (i >= G4 * HHP) return;
    int p = i / HHP, kp = i % HHP;
    int src = (p & 3) * HH + (p >> 2);
    float v0 = W[(size_t)src * HH + 2 * kp];
    float v1 = W[(size_t)src * HH + 2 * kp + 1];
    split_pair(v0, v1, hi[i], lo[i]);
}

__global__ void prep_fcnW_k(const float* __restrict__ W,
                            uint32_t* __restrict__ Wp) {
    size_t i = (size_t)blockIdx.x * blockDim.x + threadIdx.x;  // 2-pair index
    if (i * 2 >= (size_t)VOC * HHP) return;
    float4 v = *reinterpret_cast<const float4*>(&W[i * 4]);
    __half2 p0 = __floats2half2_rn(v.x, v.y);
    __half2 p1 = __floats2half2_rn(v.z, v.w);
    *reinterpret_cast<uint2*>(&Wp[i * 2]) =
        make_uint2(*reinterpret_cast<uint32_t*>(&p0),
                   *reinterpret_cast<uint32_t*>(&p1));
}

__device__ __forceinline__ float xval(const float* feat, const int* caps,
                                      const float* emb, int t, int b, int k) {
    if (k < EE) {
        int tok = (t == 0) ? 1 : caps[b * TT + (t - 1)];
        return emb[(size_t)tok * EE + k];
    }
    if (k < KRAW) return feat[b * ENC + (k - EE)];
    return 0.f;
}

__global__ void prep_X_k(const float* __restrict__ feat,
                         const int* __restrict__ caps,
                         const float* __restrict__ emb,
                         uint32_t* __restrict__ hi, uint32_t* __restrict__ lo) {
    int i = blockIdx.x * blockDim.x + threadIdx.x;
    if (i >= MX * KINP) return;
    int r = i / KINP, kp = i % KINP;
    int t = r / BB, b = r % BB;
    float v0 = xval(feat, caps, emb, t, b, 2 * kp);
    float v1 = xval(feat, caps, emb, t, b, 2 * kp + 1);
    split_pair(v0, v1, hi[i], lo[i]);
}

__global__ void zero_init_k() {
    if (blockIdx.x == 0 && threadIdx.x == 0) g_barctr = 0u;
}

// ------------------------- launch -------------------------------------------
extern "C" void kernel_launch(void* const* d_in, const int* in_sizes, int n_in,
                              void* d_out, int out_size) {
    const float* features = (const float*)d_in[0];
    const int*   captions = (const int*)d_in[1];
    const float* emb_W    = (const float*)d_in[2];
    const float* W_ih     = (const float*)d_in[3];
    const float* W_hh     = (const float*)d_in[4];
    const float* b_ih     = (const float*)d_in[5];
    const float* b_hh     = (const float*)d_in[6];
    // d_in[7..12]: attention weights — dead (softmax over a single element)
    const float* fcn_W    = (const float*)d_in[13];
    const float* fcn_b    = (const float*)d_in[14];
    float* out = (float*)d_out;

    float *bias, *Gin;
    uint32_t *Xhi, *Xlo, *WihHi, *WihLo, *WhhHi, *WhhLo, *fWp;
    uint32_t *hHiA, *hHiB, *hLoA, *hLoB, *Hb;
    cudaGetSymbolAddress((void**)&Xhi, g_Xhi);
    cudaGetSymbolAddress((void**)&Xlo, g_Xlo);
    cudaGetSymbolAddress((void**)&WihHi, g_WihHi);
    cudaGetSymbolAddress((void**)&WihLo, g_WihLo);
    cudaGetSymbolAddress((void**)&bias, g_bias);
    cudaGetSymbolAddress((void**)&Gin, g_Gin);
    cudaGetSymbolAddress((void**)&WhhHi, g_WhhHi);
    cudaGetSymbolAddress((void**)&WhhLo, g_WhhLo);
    cudaGetSymbolAddress((void**)&fWp, g_fWp);
    cudaGetSymbolAddress((void**)&hHiA, g_hHiA);
    cudaGetSymbolAddress((void**)&hHiB, g_hHiB);
    cudaGetSymbolAddress((void**)&hLoA, g_hLoA);
    cudaGetSymbolAddress((void**)&hLoB, g_hLoB);
    cudaGetSymbolAddress((void**)&Hb, g_Hb);

    constexpr int SM_IN  = (4 * 128 * 20 + 4 * 128 * 20) * 4;   // 81920
    constexpr int SM_VOC = VS * (128 * 20 + 256 * 20) * 4;      // 92160
    cudaFuncSetAttribute(gemm_in,
                         cudaFuncAttributeMaxDynamicSharedMemorySize, SM_IN);
    cudaFuncSetAttribute(gemm_vocab,
                         cudaFuncAttributeMaxDynamicSharedMemorySize, SM_VOC);
    cudaFuncSetAttribute(rec_persist,
                         cudaFuncAttributeMaxDynamicSharedMemorySize, SM_RECP);

    // prep
    prep_bias_k<<<(G4 + 255) / 256, 256>>>(b_ih, b_hh, bias);
    prep_Wih_k<<<(G4 * KINP + 255) / 256, 256>>>(W_ih, WihHi, WihLo);
    prep_Whh_k<<<(G4 * HHP + 255) / 256, 256>>>(W_hh, WhhHi, WhhLo);
    prep_fcnW_k<<<((int)((size_t)VOC * HHP / 2) + 255) / 256, 256>>>(fcn_W, fWp);
    prep_X_k<<<(MX * KINP + 255) / 256, 256>>>(features, captions, emb_W,
                                               Xhi, Xlo);
    zero_init_k<<<1, 32>>>();

    // input projection for all timesteps (permuted gate layout, bf16 split)
    gemm_in<<<dim3(G4 / 128, MX / 128), 256, SM_IN>>>(Xhi, Xlo, WihHi, WihLo,
                                                      bias);

    // full 25-step LSTM in ONE persistent kernel (128 CTAs, all resident)
    rec_persist<<<G4 / 32, 256, SM_RECP>>>(WhhHi, WhhLo, Gin,
                                           hHiA, hLoA, hHiB, hLoB, Hb);

    // batched vocab projection (plain fp16, ldmatrix, m-fastest grid)
    gemm_vocab<<<dim3(MO / 128, VOC / 256), 256, SM_VOC>>>(Hb, fWp, fcn_b,
                                                           out);
}